// round 1
// baseline (speedup 1.0000x reference)
#include <cuda_runtime.h>

#define B_  4
#define S_  1024
#define D_  512
#define H_  8
#define DK_ 64
#define MTOT (B_*S_)          // 4096 rows
#define NELE (B_*S_*D_)       // 2,097,152

// Scratch (static device globals — allowed; no cudaMalloc anywhere)
__device__ float g_q[NELE];
__device__ float g_k[NELE];
__device__ float g_v[NELE];
__device__ float g_attn[NELE];
__device__ float g_bias[(size_t)B_*S_*S_];   // bias with mask folded in (-1e9 on masked)

// ---------------------------------------------------------------------------
// SGEMM: C[M,N] = A[M,K] @ B[K,N] + bias[N]   (all row-major, M%128==0, N%128==0, K%8==0)
// 128x128 block tile, 8-deep k tile, 8x8 per-thread microtile, global prefetch.
// ---------------------------------------------------------------------------
__global__ __launch_bounds__(256) void sgemm_bias(
    const float* __restrict__ A, const float* __restrict__ Bm,
    const float* __restrict__ bias, float* __restrict__ C,
    int M, int N, int K)
{
    __shared__ float As[8 * 132];   // As[k][m], padded stride 132
    __shared__ float Bs[8 * 128];   // Bs[k][n]

    const int t  = threadIdx.x;
    const int tx = t & 15;          // n-tile index
    const int ty = t >> 4;          // m-tile index

    const int arow = t >> 1;            // 0..127
    const int acol = (t & 1) << 2;      // 0 or 4
    const int brow = t >> 5;            // 0..7
    const int bcol = (t & 31) << 2;     // 0..124

    const float* Ag = A + (size_t)(blockIdx.y * 128 + arow) * K + acol;
    const float* Bg = Bm + (size_t)brow * N + blockIdx.x * 128 + bcol;

    float acc[8][8];
    #pragma unroll
    for (int i = 0; i < 8; i++)
        #pragma unroll
        for (int j = 0; j < 8; j++) acc[i][j] = 0.f;

    float4 a_n = *(const float4*)Ag;
    float4 b_n = *(const float4*)Bg;

    for (int k0 = 0; k0 < K; k0 += 8) {
        As[(acol + 0) * 132 + arow] = a_n.x;
        As[(acol + 1) * 132 + arow] = a_n.y;
        As[(acol + 2) * 132 + arow] = a_n.z;
        As[(acol + 3) * 132 + arow] = a_n.w;
        *(float4*)&Bs[brow * 128 + bcol] = b_n;
        __syncthreads();

        if (k0 + 8 < K) {
            a_n = *(const float4*)(Ag + k0 + 8);
            b_n = *(const float4*)(Bg + (size_t)(k0 + 8) * N);
        }

        #pragma unroll
        for (int kk = 0; kk < 8; kk++) {
            float ar[8], br[8];
            *(float4*)&ar[0] = *(const float4*)&As[kk * 132 + ty * 8];
            *(float4*)&ar[4] = *(const float4*)&As[kk * 132 + ty * 8 + 4];
            *(float4*)&br[0] = *(const float4*)&Bs[kk * 128 + tx * 8];
            *(float4*)&br[4] = *(const float4*)&Bs[kk * 128 + tx * 8 + 4];
            #pragma unroll
            for (int i = 0; i < 8; i++)
                #pragma unroll
                for (int j = 0; j < 8; j++)
                    acc[i][j] += ar[i] * br[j];
        }
        __syncthreads();
    }

    const int crow0 = blockIdx.y * 128 + ty * 8;
    const int ccol0 = blockIdx.x * 128 + tx * 8;
    float bv[8];
    *(float4*)&bv[0] = *(const float4*)&bias[ccol0];
    *(float4*)&bv[4] = *(const float4*)&bias[ccol0 + 4];

    #pragma unroll
    for (int i = 0; i < 8; i++) {
        float* Cp = C + (size_t)(crow0 + i) * N + ccol0;
        float4 o0 = make_float4(acc[i][0] + bv[0], acc[i][1] + bv[1],
                                acc[i][2] + bv[2], acc[i][3] + bv[3]);
        float4 o1 = make_float4(acc[i][4] + bv[4], acc[i][5] + bv[5],
                                acc[i][6] + bv[6], acc[i][7] + bv[7]);
        *(float4*)Cp       = o0;
        *(float4*)(Cp + 4) = o1;
    }
}

// ---------------------------------------------------------------------------
// Fused bias: for each (b,i,j)
//   t = 1/log(e+T), d = 1/log(e+Dm)
//   bias = sum_m td_w[m] * (0.5*relu(d*dm_w+dm_b) + 0.5*relu(t*tm_w+tm_b)) + td_b
//   masked (mask==1) -> -1e9
// 4 elements per thread, params staged in shared.
// ---------------------------------------------------------------------------
__global__ __launch_bounds__(256) void bias_mask_kernel(
    const float* __restrict__ tmat, const float* __restrict__ dmat,
    const int*   __restrict__ mask,
    const float* __restrict__ tm_w, const float* __restrict__ tm_b,
    const float* __restrict__ dm_w, const float* __restrict__ dm_b,
    const float* __restrict__ td_w, const float* __restrict__ td_b)
{
    __shared__ float sp[5][64];
    const int t = threadIdx.x;
    if (t < 64) {
        sp[0][t] = tm_w[t];
        sp[1][t] = tm_b[t];
        sp[2][t] = dm_w[t];
        sp[3][t] = dm_b[t];
        sp[4][t] = td_w[t] * 0.5f;   // LAMBDA2 = 0.5 => both branches weighted 0.5
    }
    __syncthreads();

    const float tdb = td_b[0];
    const float E = 2.718281828459045f;

    const size_t base = ((size_t)blockIdx.x * 256 + t) * 4;
    float4 u  = *(const float4*)(tmat + base);
    float4 w  = *(const float4*)(dmat + base);
    int4   mk = *(const int4*)(mask + base);

    float tv[4] = { 1.f / __logf(E + u.x), 1.f / __logf(E + u.y),
                    1.f / __logf(E + u.z), 1.f / __logf(E + u.w) };
    float dv[4] = { 1.f / __logf(E + w.x), 1.f / __logf(E + w.y),
                    1.f / __logf(E + w.z), 1.f / __logf(E + w.w) };
    float acc[4] = { tdb, tdb, tdb, tdb };

    #pragma unroll 8
    for (int m = 0; m < 64; m++) {
        const float tw = sp[0][m], tb = sp[1][m];
        const float dw = sp[2][m], db = sp[3][m];
        const float ww = sp[4][m];
        #pragma unroll
        for (int i = 0; i < 4; i++) {
            float rt = fmaxf(tv[i] * tw + tb, 0.f);
            float rd = fmaxf(dv[i] * dw + db, 0.f);
            acc[i] += ww * (rt + rd);
        }
    }

    float4 o;
    o.x = (mk.x == 1) ? -1e9f : acc[0];
    o.y = (mk.y == 1) ? -1e9f : acc[1];
    o.z = (mk.z == 1) ? -1e9f : acc[2];
    o.w = (mk.w == 1) ? -1e9f : acc[3];
    *(float4*)(g_bias + base) = o;
}

// ---------------------------------------------------------------------------
// Flash-style attention per (qtile=64, head, batch). 64x64 kv tiles,
// online softmax. 16x16 threads, 4x4 microtiles. Output -> g_attn [B,S,D].
// ---------------------------------------------------------------------------
#define TS 68   // padded smem stride
#define SMEM_ATTN (4 * 64 * TS * 4)

__global__ __launch_bounds__(256) void attn_kernel()
{
    extern __shared__ float sm[];
    float* Qts = sm;                 // Qts[d][i]
    float* Kts = sm + 64 * TS;       // Kts[d][j]
    float* Vs  = sm + 2 * 64 * TS;   // Vs [j][n]
    float* Pts = sm + 3 * 64 * TS;   // Pts[j][i]

    const int qt = blockIdx.x, h = blockIdx.y, b = blockIdx.z;
    const int t  = threadIdx.x;
    const int tx = t & 15, ty = t >> 4;
    const int q0 = qt * 64;
    const int hoff = h * DK_;

    // Load Q tile transposed: Qts[d][i]
    #pragma unroll
    for (int r = 0; r < 4; r++) {
        int idx = t + r * 256;
        int i = idx >> 4, dv = (idx & 15) << 2;
        float4 q = *(const float4*)&g_q[(size_t)(b * S_ + q0 + i) * D_ + hoff + dv];
        Qts[(dv + 0) * TS + i] = q.x;
        Qts[(dv + 1) * TS + i] = q.y;
        Qts[(dv + 2) * TS + i] = q.z;
        Qts[(dv + 3) * TS + i] = q.w;
    }

    float m_run[4], l_run[4], O[4][4];
    #pragma unroll
    for (int ii = 0; ii < 4; ii++) {
        m_run[ii] = -1e30f; l_run[ii] = 0.f;
        #pragma unroll
        for (int nn = 0; nn < 4; nn++) O[ii][nn] = 0.f;
    }

    const float* biasRow = g_bias + ((size_t)b * S_ + q0 + ty * 4) * S_;

    for (int kt = 0; kt < 16; kt++) {
        const int k0 = kt * 64;
        __syncthreads();   // previous iteration's Vs/Pts readers done; Q writes visible

        // Load K (transposed) and V (natural)
        #pragma unroll
        for (int r = 0; r < 4; r++) {
            int idx = t + r * 256;
            int j = idx >> 4, dv = (idx & 15) << 2;
            const size_t goff = (size_t)(b * S_ + k0 + j) * D_ + hoff + dv;
            float4 kk4 = *(const float4*)&g_k[goff];
            Kts[(dv + 0) * TS + j] = kk4.x;
            Kts[(dv + 1) * TS + j] = kk4.y;
            Kts[(dv + 2) * TS + j] = kk4.z;
            Kts[(dv + 3) * TS + j] = kk4.w;
            float4 vv4 = *(const float4*)&g_v[goff];
            *(float4*)&Vs[j * TS + dv] = vv4;
        }
        __syncthreads();

        // Scores: s[ii][jj] = sum_d Q[i][d]*K[j][d]
        float s[4][4];
        #pragma unroll
        for (int ii = 0; ii < 4; ii++)
            #pragma unroll
            for (int jj = 0; jj < 4; jj++) s[ii][jj] = 0.f;

        #pragma unroll 8
        for (int d = 0; d < 64; d++) {
            float4 qv = *(const float4*)&Qts[d * TS + ty * 4];
            float4 kv = *(const float4*)&Kts[d * TS + tx * 4];
            float qa[4] = { qv.x, qv.y, qv.z, qv.w };
            float ka[4] = { kv.x, kv.y, kv.z, kv.w };
            #pragma unroll
            for (int ii = 0; ii < 4; ii++)
                #pragma unroll
                for (int jj = 0; jj < 4; jj++)
                    s[ii][jj] += qa[ii] * ka[jj];
        }

        // scale + bias (mask already folded into bias as -1e9)
        #pragma unroll
        for (int ii = 0; ii < 4; ii++) {
            float4 bb = *(const float4*)&biasRow[(size_t)ii * S_ + k0 + tx * 4];
            s[ii][0] = s[ii][0] * 0.125f + bb.x;
            s[ii][1] = s[ii][1] * 0.125f + bb.y;
            s[ii][2] = s[ii][2] * 0.125f + bb.z;
            s[ii][3] = s[ii][3] * 0.125f + bb.w;
        }

        // Row max across the 16-thread tx group (same-ty threads are 16
        // consecutive lanes; xor over bits 0..3 stays inside the group)
        float mt[4];
        #pragma unroll
        for (int ii = 0; ii < 4; ii++)
            mt[ii] = fmaxf(fmaxf(s[ii][0], s[ii][1]), fmaxf(s[ii][2], s[ii][3]));
        #pragma unroll
        for (int o = 1; o < 16; o <<= 1)
            #pragma unroll
            for (int ii = 0; ii < 4; ii++)
                mt[ii] = fmaxf(mt[ii], __shfl_xor_sync(0xffffffffu, mt[ii], o));

        float corr[4];
        #pragma unroll
        for (int ii = 0; ii < 4; ii++) {
            float mn = fmaxf(m_run[ii], mt[ii]);
            corr[ii] = __expf(m_run[ii] - mn);
            m_run[ii] = mn;
        }

        float tsum[4];
        #pragma unroll
        for (int ii = 0; ii < 4; ii++) {
            #pragma unroll
            for (int jj = 0; jj < 4; jj++)
                s[ii][jj] = __expf(s[ii][jj] - m_run[ii]);   // s becomes P
            tsum[ii] = (s[ii][0] + s[ii][1]) + (s[ii][2] + s[ii][3]);
        }
        #pragma unroll
        for (int o = 1; o < 16; o <<= 1)
            #pragma unroll
            for (int ii = 0; ii < 4; ii++)
                tsum[ii] += __shfl_xor_sync(0xffffffffu, tsum[ii], o);

        #pragma unroll
        for (int ii = 0; ii < 4; ii++) {
            l_run[ii] = l_run[ii] * corr[ii] + tsum[ii];
            #pragma unroll
            for (int nn = 0; nn < 4; nn++) O[ii][nn] *= corr[ii];
        }

        // Stage P transposed: Pts[j][i]
        #pragma unroll
        for (int jj = 0; jj < 4; jj++) {
            float4 pv = make_float4(s[0][jj], s[1][jj], s[2][jj], s[3][jj]);
            *(float4*)&Pts[(tx * 4 + jj) * TS + ty * 4] = pv;
        }
        __syncthreads();

        // O += P @ V
        #pragma unroll 8
        for (int j = 0; j < 64; j++) {
            float4 pv = *(const float4*)&Pts[j * TS + ty * 4];
            float4 vv = *(const float4*)&Vs[j * TS + tx * 4];
            float pa[4] = { pv.x, pv.y, pv.z, pv.w };
            float va[4] = { vv.x, vv.y, vv.z, vv.w };
            #pragma unroll
            for (int ii = 0; ii < 4; ii++)
                #pragma unroll
                for (int nn = 0; nn < 4; nn++)
                    O[ii][nn] += pa[ii] * va[nn];
        }
    }

    // Epilogue: normalize and write to g_attn in [B,S,D] layout
    #pragma unroll
    for (int ii = 0; ii < 4; ii++) {
        float inv = 1.f / l_run[ii];
        float4 o = make_float4(O[ii][0] * inv, O[ii][1] * inv,
                               O[ii][2] * inv, O[ii][3] * inv);
        *(float4*)&g_attn[(size_t)(b * S_ + q0 + ty * 4 + ii) * D_ + hoff + tx * 4] = o;
    }
}

// ---------------------------------------------------------------------------
extern "C" void kernel_launch(void* const* d_in, const int* in_sizes, int n_in,
                              void* d_out, int out_size)
{
    const float* Q     = (const float*)d_in[0];
    const float* K     = (const float*)d_in[1];
    const float* V     = (const float*)d_in[2];
    const float* tmat  = (const float*)d_in[3];
    const float* dmat  = (const float*)d_in[4];
    const int*   mask  = (const int*)  d_in[5];
    const float* Wq    = (const float*)d_in[6];
    const float* bq    = (const float*)d_in[7];
    const float* Wk    = (const float*)d_in[8];
    const float* bk    = (const float*)d_in[9];
    const float* Wv    = (const float*)d_in[10];
    const float* bv    = (const float*)d_in[11];
    const float* Wo    = (const float*)d_in[12];
    const float* bo    = (const float*)d_in[13];
    const float* tm_w  = (const float*)d_in[14];
    const float* tm_b  = (const float*)d_in[15];
    const float* dm_w  = (const float*)d_in[16];
    const float* dm_b  = (const float*)d_in[17];
    const float* td_w  = (const float*)d_in[18];
    const float* td_b  = (const float*)d_in[19];
    float* out = (float*)d_out;

    float *qb, *kb, *vb, *ab;
    cudaGetSymbolAddress((void**)&qb, g_q);
    cudaGetSymbolAddress((void**)&kb, g_k);
    cudaGetSymbolAddress((void**)&vb, g_v);
    cudaGetSymbolAddress((void**)&ab, g_attn);

    dim3 gg(D_ / 128, MTOT / 128);   // (4, 32)

    sgemm_bias<<<gg, 256>>>(Q, Wq, bq, qb, MTOT, D_, D_);
    sgemm_bias<<<gg, 256>>>(K, Wk, bk, kb, MTOT, D_, D_);
    sgemm_bias<<<gg, 256>>>(V, Wv, bv, vb, MTOT, D_, D_);

    bias_mask_kernel<<<(B_ * S_ * S_) / 1024, 256>>>(
        tmat, dmat, mask, tm_w, tm_b, dm_w, dm_b, td_w, td_b);

    cudaFuncSetAttribute(attn_kernel,
                         cudaFuncAttributeMaxDynamicSharedMemorySize, SMEM_ATTN);
    attn_kernel<<<dim3(S_ / 64, H_, B_), 256, SMEM_ATTN>>>();

    sgemm_bias<<<gg, 256>>>(ab, Wo, bo, out, MTOT, D_, D_);
}

// round 2
// speedup vs baseline: 1.3537x; 1.3537x over previous
#include <cuda_runtime.h>
#include <cstdint>

#define B_  4
#define S_  1024
#define D_  512
#define H_  8
#define DK_ 64
#define MTOT (B_*S_)          // 4096 rows
#define NELE (B_*S_*D_)       // 2,097,152

// Scratch (static device globals — allowed; no cudaMalloc anywhere)
__device__ float g_q[NELE];
__device__ float g_k[NELE];
__device__ float g_v[NELE];
__device__ float g_attn[NELE];
__device__ float g_bias[(size_t)B_*S_*S_];   // bias with mask folded in (-1e9 on masked)

// ---------------------------------------------------------------------------
// helpers: tf32 rounding + m16n8k8 tf32 mma
// ---------------------------------------------------------------------------
__device__ __forceinline__ float tf32f(float x) {
    uint32_t r; asm("cvt.rna.tf32.f32 %0, %1;" : "=r"(r) : "f"(x));
    return __uint_as_float(r);
}

__device__ __forceinline__ void mma8(float c[4],
    uint32_t a0, uint32_t a1, uint32_t a2, uint32_t a3,
    uint32_t b0, uint32_t b1)
{
    asm volatile(
        "mma.sync.aligned.m16n8k8.row.col.f32.tf32.tf32.f32 "
        "{%0,%1,%2,%3},{%4,%5,%6,%7},{%8,%9},{%0,%1,%2,%3};"
        : "+f"(c[0]), "+f"(c[1]), "+f"(c[2]), "+f"(c[3])
        : "r"(a0), "r"(a1), "r"(a2), "r"(a3), "r"(b0), "r"(b1));
}

// ---------------------------------------------------------------------------
// SGEMM (fp32, unchanged): C[M,N] = A[M,K] @ B[K,N] + bias[N]
// ---------------------------------------------------------------------------
__global__ __launch_bounds__(256) void sgemm_bias(
    const float* __restrict__ A, const float* __restrict__ Bm,
    const float* __restrict__ bias, float* __restrict__ C,
    int M, int N, int K)
{
    __shared__ float As[8 * 132];   // As[k][m], padded stride 132
    __shared__ float Bs[8 * 128];   // Bs[k][n]

    const int t  = threadIdx.x;
    const int tx = t & 15;
    const int ty = t >> 4;

    const int arow = t >> 1;
    const int acol = (t & 1) << 2;
    const int brow = t >> 5;
    const int bcol = (t & 31) << 2;

    const float* Ag = A + (size_t)(blockIdx.y * 128 + arow) * K + acol;
    const float* Bg = Bm + (size_t)brow * N + blockIdx.x * 128 + bcol;

    float acc[8][8];
    #pragma unroll
    for (int i = 0; i < 8; i++)
        #pragma unroll
        for (int j = 0; j < 8; j++) acc[i][j] = 0.f;

    float4 a_n = *(const float4*)Ag;
    float4 b_n = *(const float4*)Bg;

    for (int k0 = 0; k0 < K; k0 += 8) {
        As[(acol + 0) * 132 + arow] = a_n.x;
        As[(acol + 1) * 132 + arow] = a_n.y;
        As[(acol + 2) * 132 + arow] = a_n.z;
        As[(acol + 3) * 132 + arow] = a_n.w;
        *(float4*)&Bs[brow * 128 + bcol] = b_n;
        __syncthreads();

        if (k0 + 8 < K) {
            a_n = *(const float4*)(Ag + k0 + 8);
            b_n = *(const float4*)(Bg + (size_t)(k0 + 8) * N);
        }

        #pragma unroll
        for (int kk = 0; kk < 8; kk++) {
            float ar[8], br[8];
            *(float4*)&ar[0] = *(const float4*)&As[kk * 132 + ty * 8];
            *(float4*)&ar[4] = *(const float4*)&As[kk * 132 + ty * 8 + 4];
            *(float4*)&br[0] = *(const float4*)&Bs[kk * 128 + tx * 8];
            *(float4*)&br[4] = *(const float4*)&Bs[kk * 128 + tx * 8 + 4];
            #pragma unroll
            for (int i = 0; i < 8; i++)
                #pragma unroll
                for (int j = 0; j < 8; j++)
                    acc[i][j] += ar[i] * br[j];
        }
        __syncthreads();
    }

    const int crow0 = blockIdx.y * 128 + ty * 8;
    const int ccol0 = blockIdx.x * 128 + tx * 8;
    float bv[8];
    *(float4*)&bv[0] = *(const float4*)&bias[ccol0];
    *(float4*)&bv[4] = *(const float4*)&bias[ccol0 + 4];

    #pragma unroll
    for (int i = 0; i < 8; i++) {
        float* Cp = C + (size_t)(crow0 + i) * N + ccol0;
        float4 o0 = make_float4(acc[i][0] + bv[0], acc[i][1] + bv[1],
                                acc[i][2] + bv[2], acc[i][3] + bv[3]);
        float4 o1 = make_float4(acc[i][4] + bv[4], acc[i][5] + bv[5],
                                acc[i][6] + bv[6], acc[i][7] + bv[7]);
        *(float4*)Cp       = o0;
        *(float4*)(Cp + 4) = o1;
    }
}

// ---------------------------------------------------------------------------
// Fused bias + mask (unchanged)
// ---------------------------------------------------------------------------
__global__ __launch_bounds__(256) void bias_mask_kernel(
    const float* __restrict__ tmat, const float* __restrict__ dmat,
    const int*   __restrict__ mask,
    const float* __restrict__ tm_w, const float* __restrict__ tm_b,
    const float* __restrict__ dm_w, const float* __restrict__ dm_b,
    const float* __restrict__ td_w, const float* __restrict__ td_b)
{
    __shared__ float sp[5][64];
    const int t = threadIdx.x;
    if (t < 64) {
        sp[0][t] = tm_w[t];
        sp[1][t] = tm_b[t];
        sp[2][t] = dm_w[t];
        sp[3][t] = dm_b[t];
        sp[4][t] = td_w[t] * 0.5f;
    }
    __syncthreads();

    const float tdb = td_b[0];
    const float E = 2.718281828459045f;

    const size_t base = ((size_t)blockIdx.x * 256 + t) * 4;
    float4 u  = *(const float4*)(tmat + base);
    float4 w  = *(const float4*)(dmat + base);
    int4   mk = *(const int4*)(mask + base);

    float tv[4] = { 1.f / __logf(E + u.x), 1.f / __logf(E + u.y),
                    1.f / __logf(E + u.z), 1.f / __logf(E + u.w) };
    float dv[4] = { 1.f / __logf(E + w.x), 1.f / __logf(E + w.y),
                    1.f / __logf(E + w.z), 1.f / __logf(E + w.w) };
    float acc[4] = { tdb, tdb, tdb, tdb };

    #pragma unroll 8
    for (int m = 0; m < 64; m++) {
        const float tw = sp[0][m], tb = sp[1][m];
        const float dw = sp[2][m], db = sp[3][m];
        const float ww = sp[4][m];
        #pragma unroll
        for (int i = 0; i < 4; i++) {
            float rt = fmaxf(tv[i] * tw + tb, 0.f);
            float rd = fmaxf(dv[i] * dw + db, 0.f);
            acc[i] += ww * (rt + rd);
        }
    }

    float4 o;
    o.x = (mk.x == 1) ? -1e9f : acc[0];
    o.y = (mk.y == 1) ? -1e9f : acc[1];
    o.z = (mk.z == 1) ? -1e9f : acc[2];
    o.w = (mk.w == 1) ? -1e9f : acc[3];
    *(float4*)(g_bias + base) = o;
}

// ---------------------------------------------------------------------------
// Flash attention with TF32 tensor cores.
// Block = 128 threads (4 warps). Block handles one (q-tile=64, head, batch).
// Warp w owns q rows [w*16, w*16+16): scores 16x64 via m16n8k8, softmax fully
// warp-local (rows live in 4-lane shuffle groups), P staged warp-private in
// smem (tf32-rounded), then O += P@V with V as col-major B operand.
// smem strides chosen for conflict-free fragment LDS:
//   Q/K/P stride 68 (bank = 4*row + col), V stride 72 (bank = 8*j + d).
// ---------------------------------------------------------------------------
#define QS 68
#define VS 72
#define SM_K (64*QS)
#define SM_V (2*64*QS)
#define SM_P (2*64*QS + 64*VS)
#define SMEM_ATTN ((3*64*QS + 64*VS)*4)

__global__ __launch_bounds__(128) void attn_tf32()
{
    extern __shared__ float smn[];
    float* Qs = smn;
    float* Ks = smn + SM_K;
    float* Vs = smn + SM_V;
    float* Ps = smn + SM_P;

    const int qt = blockIdx.x, h = blockIdx.y, b = blockIdx.z;
    const int t = threadIdx.x;
    const int w = t >> 5, lane = t & 31;
    const int gid = lane >> 2, tig = lane & 3;
    const int q0 = qt * 64, hoff = h * DK_;
    const int r0 = w * 16 + gid;          // first row this thread owns (other: r0+8)

    // Load Q tile [64 x 64] -> smem (tf32-rounded)
    #pragma unroll
    for (int r = 0; r < 8; r++) {
        int idx = t + r * 128;
        int row = idx >> 4, c4 = (idx & 15) << 2;
        float4 q = *(const float4*)&g_q[(size_t)(b * S_ + q0 + row) * D_ + hoff + c4];
        float* dst = &Qs[row * QS + c4];
        dst[0] = tf32f(q.x); dst[1] = tf32f(q.y);
        dst[2] = tf32f(q.z); dst[3] = tf32f(q.w);
    }

    float m0 = -1e30f, m1 = -1e30f, l0 = 0.f, l1 = 0.f;
    float oacc[8][4];
    #pragma unroll
    for (int nt = 0; nt < 8; nt++)
        #pragma unroll
        for (int e = 0; e < 4; e++) oacc[nt][e] = 0.f;

    const float* biasA = g_bias + ((size_t)b * S_ + q0 + r0) * S_;
    const float* biasB = biasA + (size_t)8 * S_;

    for (int kt = 0; kt < 16; kt++) {
        const int k0 = kt * 64;
        __syncthreads();
        // Load K and V tiles [64 x 64] each (tf32-rounded)
        #pragma unroll
        for (int r = 0; r < 8; r++) {
            int idx = t + r * 128;
            int row = idx >> 4, c4 = (idx & 15) << 2;
            size_t g = (size_t)(b * S_ + k0 + row) * D_ + hoff + c4;
            float4 kk = *(const float4*)&g_k[g];
            float* kd = &Ks[row * QS + c4];
            kd[0] = tf32f(kk.x); kd[1] = tf32f(kk.y);
            kd[2] = tf32f(kk.z); kd[3] = tf32f(kk.w);
            float4 vv = *(const float4*)&g_v[g];
            float* vd = &Vs[row * VS + c4];
            vd[0] = tf32f(vv.x); vd[1] = tf32f(vv.y);
            vd[2] = tf32f(vv.z); vd[3] = tf32f(vv.w);
        }
        __syncthreads();

        // ---- scores S = Q @ K^T  (m16, n = 64 -> 8 tiles, k = 64 -> 8 steps)
        float sacc[8][4];
        #pragma unroll
        for (int nt = 0; nt < 8; nt++)
            #pragma unroll
            for (int e = 0; e < 4; e++) sacc[nt][e] = 0.f;

        const float* qa = &Qs[r0 * QS + tig];
        const float* kb = &Ks[gid * QS + tig];
        #pragma unroll
        for (int d8 = 0; d8 < 8; d8++) {
            const int d0 = d8 * 8;
            uint32_t a0 = __float_as_uint(qa[d0]);
            uint32_t a1 = __float_as_uint(qa[8 * QS + d0]);
            uint32_t a2 = __float_as_uint(qa[d0 + 4]);
            uint32_t a3 = __float_as_uint(qa[8 * QS + d0 + 4]);
            #pragma unroll
            for (int nt = 0; nt < 8; nt++) {
                uint32_t b0 = __float_as_uint(kb[nt * 8 * QS + d0]);
                uint32_t b1 = __float_as_uint(kb[nt * 8 * QS + d0 + 4]);
                mma8(sacc[nt], a0, a1, a2, a3, b0, b1);
            }
        }

        // ---- scale + bias (mask folded as -1e9) + row max
        float mx0 = -1e30f, mx1 = -1e30f;
        #pragma unroll
        for (int nt = 0; nt < 8; nt++) {
            float2 ba = *(const float2*)&biasA[k0 + nt * 8 + tig * 2];
            float2 bb = *(const float2*)&biasB[k0 + nt * 8 + tig * 2];
            sacc[nt][0] = fmaf(sacc[nt][0], 0.125f, ba.x);
            sacc[nt][1] = fmaf(sacc[nt][1], 0.125f, ba.y);
            sacc[nt][2] = fmaf(sacc[nt][2], 0.125f, bb.x);
            sacc[nt][3] = fmaf(sacc[nt][3], 0.125f, bb.y);
            mx0 = fmaxf(mx0, fmaxf(sacc[nt][0], sacc[nt][1]));
            mx1 = fmaxf(mx1, fmaxf(sacc[nt][2], sacc[nt][3]));
        }
        mx0 = fmaxf(mx0, __shfl_xor_sync(0xffffffffu, mx0, 1));
        mx0 = fmaxf(mx0, __shfl_xor_sync(0xffffffffu, mx0, 2));
        mx1 = fmaxf(mx1, __shfl_xor_sync(0xffffffffu, mx1, 1));
        mx1 = fmaxf(mx1, __shfl_xor_sync(0xffffffffu, mx1, 2));

        const float mn0 = fmaxf(m0, mx0), mn1 = fmaxf(m1, mx1);
        const float c0 = __expf(m0 - mn0), c1 = __expf(m1 - mn1);
        m0 = mn0; m1 = mn1;

        float rs0 = 0.f, rs1 = 0.f;
        #pragma unroll
        for (int nt = 0; nt < 8; nt++) {
            sacc[nt][0] = __expf(sacc[nt][0] - mn0);
            sacc[nt][1] = __expf(sacc[nt][1] - mn0);
            sacc[nt][2] = __expf(sacc[nt][2] - mn1);
            sacc[nt][3] = __expf(sacc[nt][3] - mn1);
            rs0 += sacc[nt][0] + sacc[nt][1];
            rs1 += sacc[nt][2] + sacc[nt][3];
        }
        rs0 += __shfl_xor_sync(0xffffffffu, rs0, 1);
        rs0 += __shfl_xor_sync(0xffffffffu, rs0, 2);
        rs1 += __shfl_xor_sync(0xffffffffu, rs1, 1);
        rs1 += __shfl_xor_sync(0xffffffffu, rs1, 2);

        l0 = l0 * c0 + rs0;
        l1 = l1 * c1 + rs1;
        #pragma unroll
        for (int nt = 0; nt < 8; nt++) {
            oacc[nt][0] *= c0; oacc[nt][1] *= c0;
            oacc[nt][2] *= c1; oacc[nt][3] *= c1;
        }

        // ---- stage P to warp-private smem (tf32-rounded)
        float* pr0 = &Ps[r0 * QS];
        float* pr1 = &Ps[(r0 + 8) * QS];
        #pragma unroll
        for (int nt = 0; nt < 8; nt++) {
            pr0[nt * 8 + tig * 2]     = tf32f(sacc[nt][0]);
            pr0[nt * 8 + tig * 2 + 1] = tf32f(sacc[nt][1]);
            pr1[nt * 8 + tig * 2]     = tf32f(sacc[nt][2]);
            pr1[nt * 8 + tig * 2 + 1] = tf32f(sacc[nt][3]);
        }
        __syncwarp();

        // ---- O += P @ V  (m16, n = 64 -> 8 tiles over d, k = 64 -> 8 steps over j)
        const float* pa = &Ps[r0 * QS + tig];
        const float* vb = &Vs[tig * VS + gid];
        #pragma unroll
        for (int j8 = 0; j8 < 8; j8++) {
            const int j0 = j8 * 8;
            uint32_t a0 = __float_as_uint(pa[j0]);
            uint32_t a1 = __float_as_uint(pa[8 * QS + j0]);
            uint32_t a2 = __float_as_uint(pa[j0 + 4]);
            uint32_t a3 = __float_as_uint(pa[8 * QS + j0 + 4]);
            #pragma unroll
            for (int nt = 0; nt < 8; nt++) {
                uint32_t b0 = __float_as_uint(vb[j0 * VS + nt * 8]);
                uint32_t b1 = __float_as_uint(vb[(j0 + 4) * VS + nt * 8]);
                mma8(oacc[nt], a0, a1, a2, a3, b0, b1);
            }
        }
        __syncwarp();   // P reads done before next-iter rewrite (WAR within warp)
    }

    // ---- epilogue: normalize, write [B,S,D]
    const float inv0 = 1.f / l0, inv1 = 1.f / l1;
    float* out0 = &g_attn[(size_t)(b * S_ + q0 + r0) * D_ + hoff];
    float* out1 = &g_attn[(size_t)(b * S_ + q0 + r0 + 8) * D_ + hoff];
    #pragma unroll
    for (int nt = 0; nt < 8; nt++) {
        float2 o0 = make_float2(oacc[nt][0] * inv0, oacc[nt][1] * inv0);
        float2 o1 = make_float2(oacc[nt][2] * inv1, oacc[nt][3] * inv1);
        *(float2*)&out0[nt * 8 + tig * 2] = o0;
        *(float2*)&out1[nt * 8 + tig * 2] = o1;
    }
}

// ---------------------------------------------------------------------------
extern "C" void kernel_launch(void* const* d_in, const int* in_sizes, int n_in,
                              void* d_out, int out_size)
{
    const float* Q     = (const float*)d_in[0];
    const float* K     = (const float*)d_in[1];
    const float* V     = (const float*)d_in[2];
    const float* tmat  = (const float*)d_in[3];
    const float* dmat  = (const float*)d_in[4];
    const int*   mask  = (const int*)  d_in[5];
    const float* Wq    = (const float*)d_in[6];
    const float* bq    = (const float*)d_in[7];
    const float* Wk    = (const float*)d_in[8];
    const float* bk    = (const float*)d_in[9];
    const float* Wv    = (const float*)d_in[10];
    const float* bv    = (const float*)d_in[11];
    const float* Wo    = (const float*)d_in[12];
    const float* bo    = (const float*)d_in[13];
    const float* tm_w  = (const float*)d_in[14];
    const float* tm_b  = (const float*)d_in[15];
    const float* dm_w  = (const float*)d_in[16];
    const float* dm_b  = (const float*)d_in[17];
    const float* td_w  = (const float*)d_in[18];
    const float* td_b  = (const float*)d_in[19];
    float* out = (float*)d_out;

    float *qb, *kb, *vb, *ab;
    cudaGetSymbolAddress((void**)&qb, g_q);
    cudaGetSymbolAddress((void**)&kb, g_k);
    cudaGetSymbolAddress((void**)&vb, g_v);
    cudaGetSymbolAddress((void**)&ab, g_attn);

    dim3 gg(D_ / 128, MTOT / 128);   // (4, 32)

    sgemm_bias<<<gg, 256>>>(Q, Wq, bq, qb, MTOT, D_, D_);
    sgemm_bias<<<gg, 256>>>(K, Wk, bk, kb, MTOT, D_, D_);
    sgemm_bias<<<gg, 256>>>(V, Wv, bv, vb, MTOT, D_, D_);

    bias_mask_kernel<<<(B_ * S_ * S_) / 1024, 256>>>(
        tmat, dmat, mask, tm_w, tm_b, dm_w, dm_b, td_w, td_b);

    cudaFuncSetAttribute(attn_tf32,
                         cudaFuncAttributeMaxDynamicSharedMemorySize, SMEM_ATTN);
    attn_tf32<<<dim3(S_ / 64, H_, B_), 128, SMEM_ATTN>>>();

    sgemm_bias<<<gg, 256>>>(ab, Wo, bo, out, MTOT, D_, D_);
}

// round 3
// speedup vs baseline: 2.4552x; 1.8137x over previous
#include <cuda_runtime.h>
#include <cuda_bf16.h>
#include <cstdint>

#define B_  4
#define S_  1024
#define D_  512
#define H_  8
#define DK_ 64
#define MTOT (B_*S_)          // 4096 rows
#define NELE (B_*S_*D_)       // 2,097,152

// Scratch (static device globals — allowed; no cudaMalloc anywhere)
__device__ float g_q[NELE];
__device__ float g_k[NELE];
__device__ float g_v[NELE];
__device__ float g_attn[NELE];
__device__ float g_bias[(size_t)B_*S_*S_];   // bias with mask folded in (-1e9 on masked)
__device__ float g_Ct, g_Cd;
__device__ int   g_bzero;

// ---------------------------------------------------------------------------
// helpers
// ---------------------------------------------------------------------------
__device__ __forceinline__ float tf32f(float x) {
    uint32_t r; asm("cvt.rna.tf32.f32 %0, %1;" : "=r"(r) : "f"(x));
    return __uint_as_float(r);
}

__device__ __forceinline__ void mma_tf32(float c[4],
    uint32_t a0, uint32_t a1, uint32_t a2, uint32_t a3,
    uint32_t b0, uint32_t b1)
{
    asm volatile(
        "mma.sync.aligned.m16n8k8.row.col.f32.tf32.tf32.f32 "
        "{%0,%1,%2,%3},{%4,%5,%6,%7},{%8,%9},{%0,%1,%2,%3};"
        : "+f"(c[0]), "+f"(c[1]), "+f"(c[2]), "+f"(c[3])
        : "r"(a0), "r"(a1), "r"(a2), "r"(a3), "r"(b0), "r"(b1));
}

__device__ __forceinline__ void mma_bf16(float c[4],
    uint32_t a0, uint32_t a1, uint32_t a2, uint32_t a3,
    uint32_t b0, uint32_t b1)
{
    asm volatile(
        "mma.sync.aligned.m16n8k16.row.col.f32.bf16.bf16.f32 "
        "{%0,%1,%2,%3},{%4,%5,%6,%7},{%8,%9},{%0,%1,%2,%3};"
        : "+f"(c[0]), "+f"(c[1]), "+f"(c[2]), "+f"(c[3])
        : "r"(a0), "r"(a1), "r"(a2), "r"(a3), "r"(b0), "r"(b1));
}

__device__ __forceinline__ void ldsm_x4(uint32_t& r0, uint32_t& r1,
                                        uint32_t& r2, uint32_t& r3, uint32_t addr)
{
    asm volatile("ldmatrix.sync.aligned.m8n8.x4.shared.b16 {%0,%1,%2,%3}, [%4];"
        : "=r"(r0), "=r"(r1), "=r"(r2), "=r"(r3) : "r"(addr));
}

__device__ __forceinline__ void ldsm_x2_t(uint32_t& r0, uint32_t& r1, uint32_t addr)
{
    asm volatile("ldmatrix.sync.aligned.m8n8.x2.trans.shared.b16 {%0,%1}, [%2];"
        : "=r"(r0), "=r"(r1) : "r"(addr));
}

// ---------------------------------------------------------------------------
// GEMM, bf16 tensor cores with hi/lo split (~fp32 accuracy):
//   C[M,N] = A[M,K] @ B[K,N] + bias[N]
// Block tile 128x128x32, 8 warps (4m x 2n), warp tile 32x64, mma m16n8k16.
// A staged [m][k] pad 40 (ldmatrix.x4 conflict-free),
// B staged [k][n] pad 136 (ldmatrix.x2.trans conflict-free).
// ---------------------------------------------------------------------------
#define AKP 40
#define BNP 136

__global__ __launch_bounds__(256) void gemm_bf16x3(
    const float* __restrict__ A, const float* __restrict__ Bm,
    const float* __restrict__ bias, float* __restrict__ C,
    int M, int N, int K)
{
    __shared__ __nv_bfloat16 Ash[2][128 * AKP];
    __shared__ __nv_bfloat16 Bsh[2][32 * BNP];

    const int t = threadIdx.x;
    const int lane = t & 31, wid = t >> 5;
    const int warp_m = wid & 3, warp_n = wid >> 2;
    const int m_w = warp_m * 32, n_w = warp_n * 64;
    const int bm = blockIdx.y * 128, bn = blockIdx.x * 128;
    const int gid = lane >> 2, tig = lane & 3;

    // per-thread load coords
    const int a_row = (t * 4) >> 5;             // via elem mapping below
    // A: 1024 float4s, thread does 4: elem = t + r*256
    // B: thread handles n0 = (t&63)*2, k rows kq*8..+7, kq = t>>6

    const int b_n0 = (t & 63) * 2;
    const int b_kq = (t >> 6) * 8;
    (void)a_row;

    float acc[2][8][4];
    #pragma unroll
    for (int mt = 0; mt < 2; mt++)
        #pragma unroll
        for (int nt = 0; nt < 8; nt++)
            #pragma unroll
            for (int e = 0; e < 4; e++) acc[mt][nt][e] = 0.f;

    for (int k0 = 0; k0 < K; k0 += 32) {
        __syncthreads();
        // ---- stage A [128 x 32] split into hi/lo planes
        #pragma unroll
        for (int r = 0; r < 4; r++) {
            int e = t + r * 256;
            int row = e >> 3, col4 = (e & 7) << 2;
            float4 v = *(const float4*)&A[(size_t)(bm + row) * K + k0 + col4];
            __nv_bfloat162 h0 = __floats2bfloat162_rn(v.x, v.y);
            __nv_bfloat162 h1 = __floats2bfloat162_rn(v.z, v.w);
            float2 f0 = __bfloat1622float2(h0);
            float2 f1 = __bfloat1622float2(h1);
            __nv_bfloat162 l0 = __floats2bfloat162_rn(v.x - f0.x, v.y - f0.y);
            __nv_bfloat162 l1 = __floats2bfloat162_rn(v.z - f1.x, v.w - f1.y);
            *(__nv_bfloat162*)&Ash[0][row * AKP + col4]     = h0;
            *(__nv_bfloat162*)&Ash[0][row * AKP + col4 + 2] = h1;
            *(__nv_bfloat162*)&Ash[1][row * AKP + col4]     = l0;
            *(__nv_bfloat162*)&Ash[1][row * AKP + col4 + 2] = l1;
        }
        // ---- stage B [32 x 128] split into hi/lo planes
        #pragma unroll
        for (int kk = 0; kk < 8; kk++) {
            int k = b_kq + kk;
            float2 v = *(const float2*)&Bm[(size_t)(k0 + k) * N + bn + b_n0];
            __nv_bfloat162 h = __floats2bfloat162_rn(v.x, v.y);
            float2 f = __bfloat1622float2(h);
            __nv_bfloat162 l = __floats2bfloat162_rn(v.x - f.x, v.y - f.y);
            *(__nv_bfloat162*)&Bsh[0][k * BNP + b_n0] = h;
            *(__nv_bfloat162*)&Bsh[1][k * BNP + b_n0] = l;
        }
        __syncthreads();

        // ---- compute: 2 k-blocks of 16
        #pragma unroll
        for (int kb = 0; kb < 32; kb += 16) {
            uint32_t af[2][2][4];   // [mt][plane][reg]
            #pragma unroll
            for (int mt = 0; mt < 2; mt++) {
                const int arow = m_w + mt * 16 + (lane & 15);
                const int acol = kb + ((lane >> 4) << 3);
                #pragma unroll
                for (int p = 0; p < 2; p++) {
                    uint32_t addr = (uint32_t)__cvta_generic_to_shared(
                        &Ash[p][arow * AKP + acol]);
                    ldsm_x4(af[mt][p][0], af[mt][p][1], af[mt][p][2], af[mt][p][3], addr);
                }
            }
            #pragma unroll
            for (int nt = 0; nt < 8; nt++) {
                const int brow = kb + (lane & 15);
                const int bcol = n_w + nt * 8;
                uint32_t bh0, bh1, bl0, bl1;
                uint32_t addrh = (uint32_t)__cvta_generic_to_shared(
                    &Bsh[0][brow * BNP + bcol]);
                uint32_t addrl = (uint32_t)__cvta_generic_to_shared(
                    &Bsh[1][brow * BNP + bcol]);
                ldsm_x2_t(bh0, bh1, addrh);
                ldsm_x2_t(bl0, bl1, addrl);
                #pragma unroll
                for (int mt = 0; mt < 2; mt++) {
                    mma_bf16(acc[mt][nt], af[mt][0][0], af[mt][0][1],
                             af[mt][0][2], af[mt][0][3], bh0, bh1);
                    mma_bf16(acc[mt][nt], af[mt][1][0], af[mt][1][1],
                             af[mt][1][2], af[mt][1][3], bh0, bh1);
                    mma_bf16(acc[mt][nt], af[mt][0][0], af[mt][0][1],
                             af[mt][0][2], af[mt][0][3], bl0, bl1);
                }
            }
        }
    }

    // ---- epilogue: + bias, store
    #pragma unroll
    for (int mt = 0; mt < 2; mt++) {
        const int row0 = bm + m_w + mt * 16 + gid;
        #pragma unroll
        for (int nt = 0; nt < 8; nt++) {
            const int col = bn + n_w + nt * 8 + tig * 2;
            float2 bb = *(const float2*)&bias[col];
            float2 o0 = make_float2(acc[mt][nt][0] + bb.x, acc[mt][nt][1] + bb.y);
            float2 o1 = make_float2(acc[mt][nt][2] + bb.x, acc[mt][nt][3] + bb.y);
            *(float2*)&C[(size_t)row0 * N + col]       = o0;
            *(float2*)&C[(size_t)(row0 + 8) * N + col] = o1;
        }
    }
}

// ---------------------------------------------------------------------------
// Prep: detect all-zero biases; precompute collapsed coefficients
//   bias = t*Ct + d*Cd + td_b   when tm_b == dm_b == 0 (t,d > 0 always)
// ---------------------------------------------------------------------------
__global__ void prep_kernel(const float* __restrict__ tm_w, const float* __restrict__ tm_b,
                            const float* __restrict__ dm_w, const float* __restrict__ dm_b,
                            const float* __restrict__ td_w)
{
    const int l = threadIdx.x;   // 32 threads
    float ct = 0.f, cd = 0.f;
    bool z = true;
    #pragma unroll
    for (int m = l; m < 64; m += 32) {
        z = z && (tm_b[m] == 0.f) && (dm_b[m] == 0.f);
        ct += 0.5f * td_w[m] * fmaxf(tm_w[m], 0.f);
        cd += 0.5f * td_w[m] * fmaxf(dm_w[m], 0.f);
    }
    unsigned bz = __ballot_sync(0xffffffffu, z);
    #pragma unroll
    for (int o = 16; o; o >>= 1) {
        ct += __shfl_xor_sync(0xffffffffu, ct, o);
        cd += __shfl_xor_sync(0xffffffffu, cd, o);
    }
    if (l == 0) { g_Ct = ct; g_Cd = cd; g_bzero = (bz == 0xffffffffu); }
}

// ---------------------------------------------------------------------------
// Fused bias + mask. Fast path (biases all zero): 2 FMAs per element.
// ---------------------------------------------------------------------------
__global__ __launch_bounds__(256) void bias_mask_kernel(
    const float* __restrict__ tmat, const float* __restrict__ dmat,
    const int*   __restrict__ mask,
    const float* __restrict__ tm_w, const float* __restrict__ tm_b,
    const float* __restrict__ dm_w, const float* __restrict__ dm_b,
    const float* __restrict__ td_w, const float* __restrict__ td_b)
{
    const int t = threadIdx.x;
    const float tdb = td_b[0];
    const float E = 2.718281828459045f;

    const size_t base = ((size_t)blockIdx.x * 256 + t) * 4;
    float4 u  = *(const float4*)(tmat + base);
    float4 w  = *(const float4*)(dmat + base);
    int4   mk = *(const int4*)(mask + base);

    float tv[4] = { 1.f / __logf(E + u.x), 1.f / __logf(E + u.y),
                    1.f / __logf(E + u.z), 1.f / __logf(E + u.w) };
    float dv[4] = { 1.f / __logf(E + w.x), 1.f / __logf(E + w.y),
                    1.f / __logf(E + w.z), 1.f / __logf(E + w.w) };
    float acc[4];

    if (g_bzero) {
        const float Ct = g_Ct, Cd = g_Cd;
        #pragma unroll
        for (int i = 0; i < 4; i++)
            acc[i] = fmaf(tv[i], Ct, fmaf(dv[i], Cd, tdb));
    } else {
        __shared__ float sp[5][64];
        if (t < 64) {
            sp[0][t] = tm_w[t];
            sp[1][t] = tm_b[t];
            sp[2][t] = dm_w[t];
            sp[3][t] = dm_b[t];
            sp[4][t] = td_w[t] * 0.5f;
        }
        __syncthreads();
        #pragma unroll
        for (int i = 0; i < 4; i++) acc[i] = tdb;
        #pragma unroll 8
        for (int m = 0; m < 64; m++) {
            const float tw = sp[0][m], tb = sp[1][m];
            const float dw = sp[2][m], db = sp[3][m];
            const float ww = sp[4][m];
            #pragma unroll
            for (int i = 0; i < 4; i++) {
                float rt = fmaxf(tv[i] * tw + tb, 0.f);
                float rd = fmaxf(dv[i] * dw + db, 0.f);
                acc[i] += ww * (rt + rd);
            }
        }
    }

    float4 o;
    o.x = (mk.x == 1) ? -1e9f : acc[0];
    o.y = (mk.y == 1) ? -1e9f : acc[1];
    o.z = (mk.z == 1) ? -1e9f : acc[2];
    o.w = (mk.w == 1) ? -1e9f : acc[3];
    *(float4*)(g_bias + base) = o;
}

// ---------------------------------------------------------------------------
// Flash attention with TF32 tensor cores (unchanged from R1).
// ---------------------------------------------------------------------------
#define QS 68
#define VS 72
#define SM_K (64*QS)
#define SM_V (2*64*QS)
#define SM_P (2*64*QS + 64*VS)
#define SMEM_ATTN ((3*64*QS + 64*VS)*4)

__global__ __launch_bounds__(128) void attn_tf32()
{
    extern __shared__ float smn[];
    float* Qs = smn;
    float* Ks = smn + SM_K;
    float* Vs = smn + SM_V;
    float* Ps = smn + SM_P;

    const int qt = blockIdx.x, h = blockIdx.y, b = blockIdx.z;
    const int t = threadIdx.x;
    const int w = t >> 5, lane = t & 31;
    const int gid = lane >> 2, tig = lane & 3;
    const int q0 = qt * 64, hoff = h * DK_;
    const int r0 = w * 16 + gid;

    #pragma unroll
    for (int r = 0; r < 8; r++) {
        int idx = t + r * 128;
        int row = idx >> 4, c4 = (idx & 15) << 2;
        float4 q = *(const float4*)&g_q[(size_t)(b * S_ + q0 + row) * D_ + hoff + c4];
        float* dst = &Qs[row * QS + c4];
        dst[0] = tf32f(q.x); dst[1] = tf32f(q.y);
        dst[2] = tf32f(q.z); dst[3] = tf32f(q.w);
    }

    float m0 = -1e30f, m1 = -1e30f, l0 = 0.f, l1 = 0.f;
    float oacc[8][4];
    #pragma unroll
    for (int nt = 0; nt < 8; nt++)
        #pragma unroll
        for (int e = 0; e < 4; e++) oacc[nt][e] = 0.f;

    const float* biasA = g_bias + ((size_t)b * S_ + q0 + r0) * S_;
    const float* biasB = biasA + (size_t)8 * S_;

    for (int kt = 0; kt < 16; kt++) {
        const int k0 = kt * 64;
        __syncthreads();
        #pragma unroll
        for (int r = 0; r < 8; r++) {
            int idx = t + r * 128;
            int row = idx >> 4, c4 = (idx & 15) << 2;
            size_t g = (size_t)(b * S_ + k0 + row) * D_ + hoff + c4;
            float4 kk = *(const float4*)&g_k[g];
            float* kd = &Ks[row * QS + c4];
            kd[0] = tf32f(kk.x); kd[1] = tf32f(kk.y);
            kd[2] = tf32f(kk.z); kd[3] = tf32f(kk.w);
            float4 vv = *(const float4*)&g_v[g];
            float* vd = &Vs[row * VS + c4];
            vd[0] = tf32f(vv.x); vd[1] = tf32f(vv.y);
            vd[2] = tf32f(vv.z); vd[3] = tf32f(vv.w);
        }
        __syncthreads();

        float sacc[8][4];
        #pragma unroll
        for (int nt = 0; nt < 8; nt++)
            #pragma unroll
            for (int e = 0; e < 4; e++) sacc[nt][e] = 0.f;

        const float* qa = &Qs[r0 * QS + tig];
        const float* kb = &Ks[gid * QS + tig];
        #pragma unroll
        for (int d8 = 0; d8 < 8; d8++) {
            const int d0 = d8 * 8;
            uint32_t a0 = __float_as_uint(qa[d0]);
            uint32_t a1 = __float_as_uint(qa[8 * QS + d0]);
            uint32_t a2 = __float_as_uint(qa[d0 + 4]);
            uint32_t a3 = __float_as_uint(qa[8 * QS + d0 + 4]);
            #pragma unroll
            for (int nt = 0; nt < 8; nt++) {
                uint32_t b0 = __float_as_uint(kb[nt * 8 * QS + d0]);
                uint32_t b1 = __float_as_uint(kb[nt * 8 * QS + d0 + 4]);
                mma_tf32(sacc[nt], a0, a1, a2, a3, b0, b1);
            }
        }

        float mx0 = -1e30f, mx1 = -1e30f;
        #pragma unroll
        for (int nt = 0; nt < 8; nt++) {
            float2 ba = *(const float2*)&biasA[k0 + nt * 8 + tig * 2];
            float2 bb = *(const float2*)&biasB[k0 + nt * 8 + tig * 2];
            sacc[nt][0] = fmaf(sacc[nt][0], 0.125f, ba.x);
            sacc[nt][1] = fmaf(sacc[nt][1], 0.125f, ba.y);
            sacc[nt][2] = fmaf(sacc[nt][2], 0.125f, bb.x);
            sacc[nt][3] = fmaf(sacc[nt][3], 0.125f, bb.y);
            mx0 = fmaxf(mx0, fmaxf(sacc[nt][0], sacc[nt][1]));
            mx1 = fmaxf(mx1, fmaxf(sacc[nt][2], sacc[nt][3]));
        }
        mx0 = fmaxf(mx0, __shfl_xor_sync(0xffffffffu, mx0, 1));
        mx0 = fmaxf(mx0, __shfl_xor_sync(0xffffffffu, mx0, 2));
        mx1 = fmaxf(mx1, __shfl_xor_sync(0xffffffffu, mx1, 1));
        mx1 = fmaxf(mx1, __shfl_xor_sync(0xffffffffu, mx1, 2));

        const float mn0 = fmaxf(m0, mx0), mn1 = fmaxf(m1, mx1);
        const float c0 = __expf(m0 - mn0), c1 = __expf(m1 - mn1);
        m0 = mn0; m1 = mn1;

        float rs0 = 0.f, rs1 = 0.f;
        #pragma unroll
        for (int nt = 0; nt < 8; nt++) {
            sacc[nt][0] = __expf(sacc[nt][0] - mn0);
            sacc[nt][1] = __expf(sacc[nt][1] - mn0);
            sacc[nt][2] = __expf(sacc[nt][2] - mn1);
            sacc[nt][3] = __expf(sacc[nt][3] - mn1);
            rs0 += sacc[nt][0] + sacc[nt][1];
            rs1 += sacc[nt][2] + sacc[nt][3];
        }
        rs0 += __shfl_xor_sync(0xffffffffu, rs0, 1);
        rs0 += __shfl_xor_sync(0xffffffffu, rs0, 2);
        rs1 += __shfl_xor_sync(0xffffffffu, rs1, 1);
        rs1 += __shfl_xor_sync(0xffffffffu, rs1, 2);

        l0 = l0 * c0 + rs0;
        l1 = l1 * c1 + rs1;
        #pragma unroll
        for (int nt = 0; nt < 8; nt++) {
            oacc[nt][0] *= c0; oacc[nt][1] *= c0;
            oacc[nt][2] *= c1; oacc[nt][3] *= c1;
        }

        float* pr0 = &Ps[r0 * QS];
        float* pr1 = &Ps[(r0 + 8) * QS];
        #pragma unroll
        for (int nt = 0; nt < 8; nt++) {
            pr0[nt * 8 + tig * 2]     = tf32f(sacc[nt][0]);
            pr0[nt * 8 + tig * 2 + 1] = tf32f(sacc[nt][1]);
            pr1[nt * 8 + tig * 2]     = tf32f(sacc[nt][2]);
            pr1[nt * 8 + tig * 2 + 1] = tf32f(sacc[nt][3]);
        }
        __syncwarp();

        const float* pa = &Ps[r0 * QS + tig];
        const float* vb = &Vs[tig * VS + gid];
        #pragma unroll
        for (int j8 = 0; j8 < 8; j8++) {
            const int j0 = j8 * 8;
            uint32_t a0 = __float_as_uint(pa[j0]);
            uint32_t a1 = __float_as_uint(pa[8 * QS + j0]);
            uint32_t a2 = __float_as_uint(pa[j0 + 4]);
            uint32_t a3 = __float_as_uint(pa[8 * QS + j0 + 4]);
            #pragma unroll
            for (int nt = 0; nt < 8; nt++) {
                uint32_t b0 = __float_as_uint(vb[j0 * VS + nt * 8]);
                uint32_t b1 = __float_as_uint(vb[(j0 + 4) * VS + nt * 8]);
                mma_tf32(oacc[nt], a0, a1, a2, a3, b0, b1);
            }
        }
        __syncwarp();
    }

    const float inv0 = 1.f / l0, inv1 = 1.f / l1;
    float* out0 = &g_attn[(size_t)(b * S_ + q0 + r0) * D_ + hoff];
    float* out1 = &g_attn[(size_t)(b * S_ + q0 + r0 + 8) * D_ + hoff];
    #pragma unroll
    for (int nt = 0; nt < 8; nt++) {
        float2 o0 = make_float2(oacc[nt][0] * inv0, oacc[nt][1] * inv0);
        float2 o1 = make_float2(oacc[nt][2] * inv1, oacc[nt][3] * inv1);
        *(float2*)&out0[nt * 8 + tig * 2] = o0;
        *(float2*)&out1[nt * 8 + tig * 2] = o1;
    }
}

// ---------------------------------------------------------------------------
extern "C" void kernel_launch(void* const* d_in, const int* in_sizes, int n_in,
                              void* d_out, int out_size)
{
    const float* Q     = (const float*)d_in[0];
    const float* K     = (const float*)d_in[1];
    const float* V     = (const float*)d_in[2];
    const float* tmat  = (const float*)d_in[3];
    const float* dmat  = (const float*)d_in[4];
    const int*   mask  = (const int*)  d_in[5];
    const float* Wq    = (const float*)d_in[6];
    const float* bq    = (const float*)d_in[7];
    const float* Wk    = (const float*)d_in[8];
    const float* bk    = (const float*)d_in[9];
    const float* Wv    = (const float*)d_in[10];
    const float* bv    = (const float*)d_in[11];
    const float* Wo    = (const float*)d_in[12];
    const float* bo    = (const float*)d_in[13];
    const float* tm_w  = (const float*)d_in[14];
    const float* tm_b  = (const float*)d_in[15];
    const float* dm_w  = (const float*)d_in[16];
    const float* dm_b  = (const float*)d_in[17];
    const float* td_w  = (const float*)d_in[18];
    const float* td_b  = (const float*)d_in[19];
    float* out = (float*)d_out;

    float *qb, *kb, *vb, *ab;
    cudaGetSymbolAddress((void**)&qb, g_q);
    cudaGetSymbolAddress((void**)&kb, g_k);
    cudaGetSymbolAddress((void**)&vb, g_v);
    cudaGetSymbolAddress((void**)&ab, g_attn);

    dim3 gg(D_ / 128, MTOT / 128);   // (4, 32)

    prep_kernel<<<1, 32>>>(tm_w, tm_b, dm_w, dm_b, td_w);

    gemm_bf16x3<<<gg, 256>>>(Q, Wq, bq, qb, MTOT, D_, D_);
    gemm_bf16x3<<<gg, 256>>>(K, Wk, bk, kb, MTOT, D_, D_);
    gemm_bf16x3<<<gg, 256>>>(V, Wv, bv, vb, MTOT, D_, D_);

    bias_mask_kernel<<<(B_ * S_ * S_) / 1024, 256>>>(
        tmat, dmat, mask, tm_w, tm_b, dm_w, dm_b, td_w, td_b);

    cudaFuncSetAttribute(attn_tf32,
                         cudaFuncAttributeMaxDynamicSharedMemorySize, SMEM_ATTN);
    attn_tf32<<<dim3(S_ / 64, H_, B_), 128, SMEM_ATTN>>>();

    gemm_bf16x3<<<gg, 256>>>(ab, Wo, bo, out, MTOT, D_, D_);
}

// round 4
// speedup vs baseline: 2.7624x; 1.1251x over previous
#include <cuda_runtime.h>
#include <cuda_bf16.h>
#include <cstdint>

#define B_  4
#define S_  1024
#define D_  512
#define H_  8
#define DK_ 64
#define MTOT (B_*S_)          // 4096 rows
#define NELE (B_*S_*D_)       // 2,097,152

// Scratch (static device globals — allowed; no cudaMalloc anywhere)
__device__ float g_q[NELE];
__device__ float g_k[NELE];
__device__ float g_v[NELE];
__device__ float g_attn[NELE];
__device__ float g_bias[(size_t)B_*S_*S_];   // bias with mask folded in (-1e9 on masked)
__device__ float g_Ct, g_Cd;
__device__ int   g_bzero;

// ---------------------------------------------------------------------------
// helpers
// ---------------------------------------------------------------------------
__device__ __forceinline__ float tf32f(float x) {
    uint32_t r; asm("cvt.rna.tf32.f32 %0, %1;" : "=r"(r) : "f"(x));
    return __uint_as_float(r);
}

__device__ __forceinline__ void mma_tf32(float c[4],
    uint32_t a0, uint32_t a1, uint32_t a2, uint32_t a3,
    uint32_t b0, uint32_t b1)
{
    asm volatile(
        "mma.sync.aligned.m16n8k8.row.col.f32.tf32.tf32.f32 "
        "{%0,%1,%2,%3},{%4,%5,%6,%7},{%8,%9},{%0,%1,%2,%3};"
        : "+f"(c[0]), "+f"(c[1]), "+f"(c[2]), "+f"(c[3])
        : "r"(a0), "r"(a1), "r"(a2), "r"(a3), "r"(b0), "r"(b1));
}

__device__ __forceinline__ void mma_bf16(float c[4],
    uint32_t a0, uint32_t a1, uint32_t a2, uint32_t a3,
    uint32_t b0, uint32_t b1)
{
    asm volatile(
        "mma.sync.aligned.m16n8k16.row.col.f32.bf16.bf16.f32 "
        "{%0,%1,%2,%3},{%4,%5,%6,%7},{%8,%9},{%0,%1,%2,%3};"
        : "+f"(c[0]), "+f"(c[1]), "+f"(c[2]), "+f"(c[3])
        : "r"(a0), "r"(a1), "r"(a2), "r"(a3), "r"(b0), "r"(b1));
}

__device__ __forceinline__ void ldsm_x4(uint32_t& r0, uint32_t& r1,
                                        uint32_t& r2, uint32_t& r3, uint32_t addr)
{
    asm volatile("ldmatrix.sync.aligned.m8n8.x4.shared.b16 {%0,%1,%2,%3}, [%4];"
        : "=r"(r0), "=r"(r1), "=r"(r2), "=r"(r3) : "r"(addr));
}

__device__ __forceinline__ void ldsm_x2_t(uint32_t& r0, uint32_t& r1, uint32_t addr)
{
    asm volatile("ldmatrix.sync.aligned.m8n8.x2.trans.shared.b16 {%0,%1}, [%2];"
        : "=r"(r0), "=r"(r1) : "r"(addr));
}

// ---------------------------------------------------------------------------
// Fused GEMM (up to 3 problems via blockIdx.z), bf16 TC with hi/lo split:
//   C[M,N] = A[M,K] @ W[K,N] + bias[N]
// Block tile 128x128x32, 8 warps (4m x 2n), warp tile 32x64, mma m16n8k16.
// Register-prefetch pipelining: next k-tile global loads issued right after
// the post-store barrier, so they overlap the mma work on the current tile.
// ---------------------------------------------------------------------------
#define AKP 40
#define BNP 136

__global__ __launch_bounds__(256) void gemm_qkv(
    const float* __restrict__ A0, const float* __restrict__ A1, const float* __restrict__ A2,
    const float* __restrict__ W0, const float* __restrict__ W1, const float* __restrict__ W2,
    const float* __restrict__ b0v, const float* __restrict__ b1v, const float* __restrict__ b2v,
    float* __restrict__ C0, float* __restrict__ C1, float* __restrict__ C2,
    int M, int N, int K)
{
    __shared__ __nv_bfloat16 Ash[2][128 * AKP];
    __shared__ __nv_bfloat16 Bsh[2][32 * BNP];

    const float* A;  const float* Wm; const float* bias; float* C;
    if (blockIdx.z == 0)      { A = A0; Wm = W0; bias = b0v; C = C0; }
    else if (blockIdx.z == 1) { A = A1; Wm = W1; bias = b1v; C = C1; }
    else                      { A = A2; Wm = W2; bias = b2v; C = C2; }

    const int t = threadIdx.x;
    const int lane = t & 31, wid = t >> 5;
    const int warp_m = wid & 3, warp_n = wid >> 2;
    const int m_w = warp_m * 32, n_w = warp_n * 64;
    const int bm = blockIdx.y * 128, bn = blockIdx.x * 128;
    const int gid = lane >> 2, tig = lane & 3;

    const int b_n0 = (t & 63) * 2;
    const int b_kq = (t >> 6) * 8;

    float acc[2][8][4];
    #pragma unroll
    for (int mt = 0; mt < 2; mt++)
        #pragma unroll
        for (int nt = 0; nt < 8; nt++)
            #pragma unroll
            for (int e = 0; e < 4; e++) acc[mt][nt][e] = 0.f;

    // ---- initial prefetch (k0 = 0)
    float4 a_pre[4];
    float2 b_pre[8];
    #pragma unroll
    for (int r = 0; r < 4; r++) {
        int e = t + r * 256;
        int row = e >> 3, col4 = (e & 7) << 2;
        a_pre[r] = *(const float4*)&A[(size_t)(bm + row) * K + col4];
    }
    #pragma unroll
    for (int kk = 0; kk < 8; kk++)
        b_pre[kk] = *(const float2*)&Wm[(size_t)(b_kq + kk) * N + bn + b_n0];

    for (int k0 = 0; k0 < K; k0 += 32) {
        // ---- convert + store staged registers to smem (hi/lo planes)
        #pragma unroll
        for (int r = 0; r < 4; r++) {
            int e = t + r * 256;
            int row = e >> 3, col4 = (e & 7) << 2;
            float4 v = a_pre[r];
            __nv_bfloat162 h0 = __floats2bfloat162_rn(v.x, v.y);
            __nv_bfloat162 h1 = __floats2bfloat162_rn(v.z, v.w);
            float2 f0 = __bfloat1622float2(h0);
            float2 f1 = __bfloat1622float2(h1);
            __nv_bfloat162 l0 = __floats2bfloat162_rn(v.x - f0.x, v.y - f0.y);
            __nv_bfloat162 l1 = __floats2bfloat162_rn(v.z - f1.x, v.w - f1.y);
            *(__nv_bfloat162*)&Ash[0][row * AKP + col4]     = h0;
            *(__nv_bfloat162*)&Ash[0][row * AKP + col4 + 2] = h1;
            *(__nv_bfloat162*)&Ash[1][row * AKP + col4]     = l0;
            *(__nv_bfloat162*)&Ash[1][row * AKP + col4 + 2] = l1;
        }
        #pragma unroll
        for (int kk = 0; kk < 8; kk++) {
            int k = b_kq + kk;
            float2 v = b_pre[kk];
            __nv_bfloat162 h = __floats2bfloat162_rn(v.x, v.y);
            float2 f = __bfloat1622float2(h);
            __nv_bfloat162 l = __floats2bfloat162_rn(v.x - f.x, v.y - f.y);
            *(__nv_bfloat162*)&Bsh[0][k * BNP + b_n0] = h;
            *(__nv_bfloat162*)&Bsh[1][k * BNP + b_n0] = l;
        }
        __syncthreads();

        // ---- prefetch next k-tile while computing this one
        if (k0 + 32 < K) {
            #pragma unroll
            for (int r = 0; r < 4; r++) {
                int e = t + r * 256;
                int row = e >> 3, col4 = (e & 7) << 2;
                a_pre[r] = *(const float4*)&A[(size_t)(bm + row) * K + k0 + 32 + col4];
            }
            #pragma unroll
            for (int kk = 0; kk < 8; kk++)
                b_pre[kk] = *(const float2*)&Wm[(size_t)(k0 + 32 + b_kq + kk) * N + bn + b_n0];
        }

        // ---- compute: 2 k-blocks of 16
        #pragma unroll
        for (int kb = 0; kb < 32; kb += 16) {
            uint32_t af[2][2][4];   // [mt][plane][reg]
            #pragma unroll
            for (int mt = 0; mt < 2; mt++) {
                const int arow = m_w + mt * 16 + (lane & 15);
                const int acol = kb + ((lane >> 4) << 3);
                #pragma unroll
                for (int p = 0; p < 2; p++) {
                    uint32_t addr = (uint32_t)__cvta_generic_to_shared(
                        &Ash[p][arow * AKP + acol]);
                    ldsm_x4(af[mt][p][0], af[mt][p][1], af[mt][p][2], af[mt][p][3], addr);
                }
            }
            #pragma unroll
            for (int nt = 0; nt < 8; nt++) {
                const int brow = kb + (lane & 15);
                const int bcol = n_w + nt * 8;
                uint32_t bh0, bh1, bl0, bl1;
                uint32_t addrh = (uint32_t)__cvta_generic_to_shared(
                    &Bsh[0][brow * BNP + bcol]);
                uint32_t addrl = (uint32_t)__cvta_generic_to_shared(
                    &Bsh[1][brow * BNP + bcol]);
                ldsm_x2_t(bh0, bh1, addrh);
                ldsm_x2_t(bl0, bl1, addrl);
                #pragma unroll
                for (int mt = 0; mt < 2; mt++) {
                    mma_bf16(acc[mt][nt], af[mt][0][0], af[mt][0][1],
                             af[mt][0][2], af[mt][0][3], bh0, bh1);
                    mma_bf16(acc[mt][nt], af[mt][1][0], af[mt][1][1],
                             af[mt][1][2], af[mt][1][3], bh0, bh1);
                    mma_bf16(acc[mt][nt], af[mt][0][0], af[mt][0][1],
                             af[mt][0][2], af[mt][0][3], bl0, bl1);
                }
            }
        }
        __syncthreads();
    }

    // ---- epilogue: + bias, store
    #pragma unroll
    for (int mt = 0; mt < 2; mt++) {
        const int row0 = bm + m_w + mt * 16 + gid;
        #pragma unroll
        for (int nt = 0; nt < 8; nt++) {
            const int col = bn + n_w + nt * 8 + tig * 2;
            float2 bb = *(const float2*)&bias[col];
            float2 o0 = make_float2(acc[mt][nt][0] + bb.x, acc[mt][nt][1] + bb.y);
            float2 o1 = make_float2(acc[mt][nt][2] + bb.x, acc[mt][nt][3] + bb.y);
            *(float2*)&C[(size_t)row0 * N + col]       = o0;
            *(float2*)&C[(size_t)(row0 + 8) * N + col] = o1;
        }
    }
}

// ---------------------------------------------------------------------------
// Prep: detect all-zero biases; precompute collapsed coefficients
// ---------------------------------------------------------------------------
__global__ void prep_kernel(const float* __restrict__ tm_w, const float* __restrict__ tm_b,
                            const float* __restrict__ dm_w, const float* __restrict__ dm_b,
                            const float* __restrict__ td_w)
{
    const int l = threadIdx.x;   // 32 threads
    float ct = 0.f, cd = 0.f;
    bool z = true;
    #pragma unroll
    for (int m = l; m < 64; m += 32) {
        z = z && (tm_b[m] == 0.f) && (dm_b[m] == 0.f);
        ct += 0.5f * td_w[m] * fmaxf(tm_w[m], 0.f);
        cd += 0.5f * td_w[m] * fmaxf(dm_w[m], 0.f);
    }
    unsigned bz = __ballot_sync(0xffffffffu, z);
    #pragma unroll
    for (int o = 16; o; o >>= 1) {
        ct += __shfl_xor_sync(0xffffffffu, ct, o);
        cd += __shfl_xor_sync(0xffffffffu, cd, o);
    }
    if (l == 0) { g_Ct = ct; g_Cd = cd; g_bzero = (bz == 0xffffffffu); }
}

// ---------------------------------------------------------------------------
// Fused bias + mask. Fast path (biases all zero): 2 FMAs per element.
// ---------------------------------------------------------------------------
__global__ __launch_bounds__(256) void bias_mask_kernel(
    const float* __restrict__ tmat, const float* __restrict__ dmat,
    const int*   __restrict__ mask,
    const float* __restrict__ tm_w, const float* __restrict__ tm_b,
    const float* __restrict__ dm_w, const float* __restrict__ dm_b,
    const float* __restrict__ td_w, const float* __restrict__ td_b)
{
    const int t = threadIdx.x;
    const float tdb = td_b[0];
    const float E = 2.718281828459045f;

    const size_t base = ((size_t)blockIdx.x * 256 + t) * 4;
    float4 u  = *(const float4*)(tmat + base);
    float4 w  = *(const float4*)(dmat + base);
    int4   mk = *(const int4*)(mask + base);

    float tv[4] = { 1.f / __logf(E + u.x), 1.f / __logf(E + u.y),
                    1.f / __logf(E + u.z), 1.f / __logf(E + u.w) };
    float dv[4] = { 1.f / __logf(E + w.x), 1.f / __logf(E + w.y),
                    1.f / __logf(E + w.z), 1.f / __logf(E + w.w) };
    float acc[4];

    if (g_bzero) {
        const float Ct = g_Ct, Cd = g_Cd;
        #pragma unroll
        for (int i = 0; i < 4; i++)
            acc[i] = fmaf(tv[i], Ct, fmaf(dv[i], Cd, tdb));
    } else {
        __shared__ float sp[5][64];
        if (t < 64) {
            sp[0][t] = tm_w[t];
            sp[1][t] = tm_b[t];
            sp[2][t] = dm_w[t];
            sp[3][t] = dm_b[t];
            sp[4][t] = td_w[t] * 0.5f;
        }
        __syncthreads();
        #pragma unroll
        for (int i = 0; i < 4; i++) acc[i] = tdb;
        #pragma unroll 8
        for (int m = 0; m < 64; m++) {
            const float tw = sp[0][m], tb = sp[1][m];
            const float dw = sp[2][m], db = sp[3][m];
            const float ww = sp[4][m];
            #pragma unroll
            for (int i = 0; i < 4; i++) {
                float rt = fmaxf(tv[i] * tw + tb, 0.f);
                float rd = fmaxf(dv[i] * dw + db, 0.f);
                acc[i] += ww * (rt + rd);
            }
        }
    }

    float4 o;
    o.x = (mk.x == 1) ? -1e9f : acc[0];
    o.y = (mk.y == 1) ? -1e9f : acc[1];
    o.z = (mk.z == 1) ? -1e9f : acc[2];
    o.w = (mk.w == 1) ? -1e9f : acc[3];
    *(float4*)(g_bias + base) = o;
}

// ---------------------------------------------------------------------------
// Flash attention with TF32 tensor cores (unchanged).
// ---------------------------------------------------------------------------
#define QS 68
#define VS 72
#define SM_K (64*QS)
#define SM_V (2*64*QS)
#define SM_P (2*64*QS + 64*VS)
#define SMEM_ATTN ((3*64*QS + 64*VS)*4)

__global__ __launch_bounds__(128) void attn_tf32()
{
    extern __shared__ float smn[];
    float* Qs = smn;
    float* Ks = smn + SM_K;
    float* Vs = smn + SM_V;
    float* Ps = smn + SM_P;

    const int qt = blockIdx.x, h = blockIdx.y, b = blockIdx.z;
    const int t = threadIdx.x;
    const int w = t >> 5, lane = t & 31;
    const int gid = lane >> 2, tig = lane & 3;
    const int q0 = qt * 64, hoff = h * DK_;
    const int r0 = w * 16 + gid;

    #pragma unroll
    for (int r = 0; r < 8; r++) {
        int idx = t + r * 128;
        int row = idx >> 4, c4 = (idx & 15) << 2;
        float4 q = *(const float4*)&g_q[(size_t)(b * S_ + q0 + row) * D_ + hoff + c4];
        float* dst = &Qs[row * QS + c4];
        dst[0] = tf32f(q.x); dst[1] = tf32f(q.y);
        dst[2] = tf32f(q.z); dst[3] = tf32f(q.w);
    }

    float m0 = -1e30f, m1 = -1e30f, l0 = 0.f, l1 = 0.f;
    float oacc[8][4];
    #pragma unroll
    for (int nt = 0; nt < 8; nt++)
        #pragma unroll
        for (int e = 0; e < 4; e++) oacc[nt][e] = 0.f;

    const float* biasA = g_bias + ((size_t)b * S_ + q0 + r0) * S_;
    const float* biasB = biasA + (size_t)8 * S_;

    for (int kt = 0; kt < 16; kt++) {
        const int k0 = kt * 64;
        __syncthreads();
        #pragma unroll
        for (int r = 0; r < 8; r++) {
            int idx = t + r * 128;
            int row = idx >> 4, c4 = (idx & 15) << 2;
            size_t g = (size_t)(b * S_ + k0 + row) * D_ + hoff + c4;
            float4 kk = *(const float4*)&g_k[g];
            float* kd = &Ks[row * QS + c4];
            kd[0] = tf32f(kk.x); kd[1] = tf32f(kk.y);
            kd[2] = tf32f(kk.z); kd[3] = tf32f(kk.w);
            float4 vv = *(const float4*)&g_v[g];
            float* vd = &Vs[row * VS + c4];
            vd[0] = tf32f(vv.x); vd[1] = tf32f(vv.y);
            vd[2] = tf32f(vv.z); vd[3] = tf32f(vv.w);
        }
        __syncthreads();

        float sacc[8][4];
        #pragma unroll
        for (int nt = 0; nt < 8; nt++)
            #pragma unroll
            for (int e = 0; e < 4; e++) sacc[nt][e] = 0.f;

        const float* qa = &Qs[r0 * QS + tig];
        const float* kb = &Ks[gid * QS + tig];
        #pragma unroll
        for (int d8 = 0; d8 < 8; d8++) {
            const int d0 = d8 * 8;
            uint32_t a0 = __float_as_uint(qa[d0]);
            uint32_t a1 = __float_as_uint(qa[8 * QS + d0]);
            uint32_t a2 = __float_as_uint(qa[d0 + 4]);
            uint32_t a3 = __float_as_uint(qa[8 * QS + d0 + 4]);
            #pragma unroll
            for (int nt = 0; nt < 8; nt++) {
                uint32_t b0 = __float_as_uint(kb[nt * 8 * QS + d0]);
                uint32_t b1 = __float_as_uint(kb[nt * 8 * QS + d0 + 4]);
                mma_tf32(sacc[nt], a0, a1, a2, a3, b0, b1);
            }
        }

        float mx0 = -1e30f, mx1 = -1e30f;
        #pragma unroll
        for (int nt = 0; nt < 8; nt++) {
            float2 ba = *(const float2*)&biasA[k0 + nt * 8 + tig * 2];
            float2 bb = *(const float2*)&biasB[k0 + nt * 8 + tig * 2];
            sacc[nt][0] = fmaf(sacc[nt][0], 0.125f, ba.x);
            sacc[nt][1] = fmaf(sacc[nt][1], 0.125f, ba.y);
            sacc[nt][2] = fmaf(sacc[nt][2], 0.125f, bb.x);
            sacc[nt][3] = fmaf(sacc[nt][3], 0.125f, bb.y);
            mx0 = fmaxf(mx0, fmaxf(sacc[nt][0], sacc[nt][1]));
            mx1 = fmaxf(mx1, fmaxf(sacc[nt][2], sacc[nt][3]));
        }
        mx0 = fmaxf(mx0, __shfl_xor_sync(0xffffffffu, mx0, 1));
        mx0 = fmaxf(mx0, __shfl_xor_sync(0xffffffffu, mx0, 2));
        mx1 = fmaxf(mx1, __shfl_xor_sync(0xffffffffu, mx1, 1));
        mx1 = fmaxf(mx1, __shfl_xor_sync(0xffffffffu, mx1, 2));

        const float mn0 = fmaxf(m0, mx0), mn1 = fmaxf(m1, mx1);
        const float c0 = __expf(m0 - mn0), c1 = __expf(m1 - mn1);
        m0 = mn0; m1 = mn1;

        float rs0 = 0.f, rs1 = 0.f;
        #pragma unroll
        for (int nt = 0; nt < 8; nt++) {
            sacc[nt][0] = __expf(sacc[nt][0] - mn0);
            sacc[nt][1] = __expf(sacc[nt][1] - mn0);
            sacc[nt][2] = __expf(sacc[nt][2] - mn1);
            sacc[nt][3] = __expf(sacc[nt][3] - mn1);
            rs0 += sacc[nt][0] + sacc[nt][1];
            rs1 += sacc[nt][2] + sacc[nt][3];
        }
        rs0 += __shfl_xor_sync(0xffffffffu, rs0, 1);
        rs0 += __shfl_xor_sync(0xffffffffu, rs0, 2);
        rs1 += __shfl_xor_sync(0xffffffffu, rs1, 1);
        rs1 += __shfl_xor_sync(0xffffffffu, rs1, 2);

        l0 = l0 * c0 + rs0;
        l1 = l1 * c1 + rs1;
        #pragma unroll
        for (int nt = 0; nt < 8; nt++) {
            oacc[nt][0] *= c0; oacc[nt][1] *= c0;
            oacc[nt][2] *= c1; oacc[nt][3] *= c1;
        }

        float* pr0 = &Ps[r0 * QS];
        float* pr1 = &Ps[(r0 + 8) * QS];
        #pragma unroll
        for (int nt = 0; nt < 8; nt++) {
            pr0[nt * 8 + tig * 2]     = tf32f(sacc[nt][0]);
            pr0[nt * 8 + tig * 2 + 1] = tf32f(sacc[nt][1]);
            pr1[nt * 8 + tig * 2]     = tf32f(sacc[nt][2]);
            pr1[nt * 8 + tig * 2 + 1] = tf32f(sacc[nt][3]);
        }
        __syncwarp();

        const float* pa = &Ps[r0 * QS + tig];
        const float* vb = &Vs[tig * VS + gid];
        #pragma unroll
        for (int j8 = 0; j8 < 8; j8++) {
            const int j0 = j8 * 8;
            uint32_t a0 = __float_as_uint(pa[j0]);
            uint32_t a1 = __float_as_uint(pa[8 * QS + j0]);
            uint32_t a2 = __float_as_uint(pa[j0 + 4]);
            uint32_t a3 = __float_as_uint(pa[8 * QS + j0 + 4]);
            #pragma unroll
            for (int nt = 0; nt < 8; nt++) {
                uint32_t b0 = __float_as_uint(vb[j0 * VS + nt * 8]);
                uint32_t b1 = __float_as_uint(vb[(j0 + 4) * VS + nt * 8]);
                mma_tf32(oacc[nt], a0, a1, a2, a3, b0, b1);
            }
        }
        __syncwarp();
    }

    const float inv0 = 1.f / l0, inv1 = 1.f / l1;
    float* out0 = &g_attn[(size_t)(b * S_ + q0 + r0) * D_ + hoff];
    float* out1 = &g_attn[(size_t)(b * S_ + q0 + r0 + 8) * D_ + hoff];
    #pragma unroll
    for (int nt = 0; nt < 8; nt++) {
        float2 o0 = make_float2(oacc[nt][0] * inv0, oacc[nt][1] * inv0);
        float2 o1 = make_float2(oacc[nt][2] * inv1, oacc[nt][3] * inv1);
        *(float2*)&out0[nt * 8 + tig * 2] = o0;
        *(float2*)&out1[nt * 8 + tig * 2] = o1;
    }
}

// ---------------------------------------------------------------------------
extern "C" void kernel_launch(void* const* d_in, const int* in_sizes, int n_in,
                              void* d_out, int out_size)
{
    const float* Q     = (const float*)d_in[0];
    const float* K     = (const float*)d_in[1];
    const float* V     = (const float*)d_in[2];
    const float* tmat  = (const float*)d_in[3];
    const float* dmat  = (const float*)d_in[4];
    const int*   mask  = (const int*)  d_in[5];
    const float* Wq    = (const float*)d_in[6];
    const float* bq    = (const float*)d_in[7];
    const float* Wk    = (const float*)d_in[8];
    const float* bk    = (const float*)d_in[9];
    const float* Wv    = (const float*)d_in[10];
    const float* bv    = (const float*)d_in[11];
    const float* Wo    = (const float*)d_in[12];
    const float* bo    = (const float*)d_in[13];
    const float* tm_w  = (const float*)d_in[14];
    const float* tm_b  = (const float*)d_in[15];
    const float* dm_w  = (const float*)d_in[16];
    const float* dm_b  = (const float*)d_in[17];
    const float* td_w  = (const float*)d_in[18];
    const float* td_b  = (const float*)d_in[19];
    float* out = (float*)d_out;

    float *qb, *kb, *vb, *ab;
    cudaGetSymbolAddress((void**)&qb, g_q);
    cudaGetSymbolAddress((void**)&kb, g_k);
    cudaGetSymbolAddress((void**)&vb, g_v);
    cudaGetSymbolAddress((void**)&ab, g_attn);

    prep_kernel<<<1, 32>>>(tm_w, tm_b, dm_w, dm_b, td_w);

    // fused Q/K/V projections (z = 3)
    gemm_qkv<<<dim3(D_ / 128, MTOT / 128, 3), 256>>>(
        Q, K, V, Wq, Wk, Wv, bq, bk, bv, qb, kb, vb, MTOT, D_, D_);

    bias_mask_kernel<<<(B_ * S_ * S_) / 1024, 256>>>(
        tmat, dmat, mask, tm_w, tm_b, dm_w, dm_b, td_w, td_b);

    cudaFuncSetAttribute(attn_tf32,
                         cudaFuncAttributeMaxDynamicSharedMemorySize, SMEM_ATTN);
    attn_tf32<<<dim3(S_ / 64, H_, B_), 128, SMEM_ATTN>>>();

    // output projection (z = 1; reuse fused kernel, slot 0)
    gemm_qkv<<<dim3(D_ / 128, MTOT / 128, 1), 256>>>(
        ab, ab, ab, Wo, Wo, Wo, bo, bo, bo, out, out, out, MTOT, D_, D_);
}

// round 5
// speedup vs baseline: 2.9140x; 1.0549x over previous
#include <cuda_runtime.h>
#include <cuda_bf16.h>
#include <cstdint>

#define B_  4
#define S_  1024
#define D_  512
#define H_  8
#define DK_ 64
#define MTOT (B_*S_)          // 4096 rows
#define NELE (B_*S_*D_)       // 2,097,152

// Scratch (static device globals — allowed; no cudaMalloc anywhere)
__device__ float g_q[NELE];          // tf32-rounded, pre-scaled by 1/8
__device__ float g_k[NELE];          // tf32-rounded
__device__ float g_v[NELE];          // tf32-rounded
__device__ float g_attn[NELE];
__device__ float g_bias[(size_t)B_*S_*S_];   // bias with mask folded in (-1e9 on masked)
__device__ float g_Ct, g_Cd;
__device__ int   g_bzero;

// ---------------------------------------------------------------------------
// helpers
// ---------------------------------------------------------------------------
__device__ __forceinline__ float tf32f(float x) {
    uint32_t r; asm("cvt.rna.tf32.f32 %0, %1;" : "=r"(r) : "f"(x));
    return __uint_as_float(r);
}

__device__ __forceinline__ void mma_tf32(float c[4],
    uint32_t a0, uint32_t a1, uint32_t a2, uint32_t a3,
    uint32_t b0, uint32_t b1)
{
    asm volatile(
        "mma.sync.aligned.m16n8k8.row.col.f32.tf32.tf32.f32 "
        "{%0,%1,%2,%3},{%4,%5,%6,%7},{%8,%9},{%0,%1,%2,%3};"
        : "+f"(c[0]), "+f"(c[1]), "+f"(c[2]), "+f"(c[3])
        : "r"(a0), "r"(a1), "r"(a2), "r"(a3), "r"(b0), "r"(b1));
}

__device__ __forceinline__ void mma_bf16(float c[4],
    uint32_t a0, uint32_t a1, uint32_t a2, uint32_t a3,
    uint32_t b0, uint32_t b1)
{
    asm volatile(
        "mma.sync.aligned.m16n8k16.row.col.f32.bf16.bf16.f32 "
        "{%0,%1,%2,%3},{%4,%5,%6,%7},{%8,%9},{%0,%1,%2,%3};"
        : "+f"(c[0]), "+f"(c[1]), "+f"(c[2]), "+f"(c[3])
        : "r"(a0), "r"(a1), "r"(a2), "r"(a3), "r"(b0), "r"(b1));
}

__device__ __forceinline__ void ldsm_x4(uint32_t& r0, uint32_t& r1,
                                        uint32_t& r2, uint32_t& r3, uint32_t addr)
{
    asm volatile("ldmatrix.sync.aligned.m8n8.x4.shared.b16 {%0,%1,%2,%3}, [%4];"
        : "=r"(r0), "=r"(r1), "=r"(r2), "=r"(r3) : "r"(addr));
}

__device__ __forceinline__ void ldsm_x2_t(uint32_t& r0, uint32_t& r1, uint32_t addr)
{
    asm volatile("ldmatrix.sync.aligned.m8n8.x2.trans.shared.b16 {%0,%1}, [%2];"
        : "=r"(r0), "=r"(r1) : "r"(addr));
}

__device__ __forceinline__ void cpa16(uint32_t dst, const float* src) {
    asm volatile("cp.async.cg.shared.global [%0], [%1], 16;" :: "r"(dst), "l"(src));
}
__device__ __forceinline__ void cp_commit() {
    asm volatile("cp.async.commit_group;");
}
template<int N> __device__ __forceinline__ void cp_wait() {
    asm volatile("cp.async.wait_group %0;" :: "n"(N));
}

// ---------------------------------------------------------------------------
// Fused GEMM (up to 3 problems via blockIdx.z), bf16 TC with hi/lo split:
//   C[M,N] = (A[M,K] @ W[K,N] + bias[N]) * (z==0 ? scale0 : 1), opt tf32-round
// ---------------------------------------------------------------------------
#define AKP 40
#define BNP 136

__global__ __launch_bounds__(256) void gemm_qkv(
    const float* __restrict__ A0, const float* __restrict__ A1, const float* __restrict__ A2,
    const float* __restrict__ W0, const float* __restrict__ W1, const float* __restrict__ W2,
    const float* __restrict__ b0v, const float* __restrict__ b1v, const float* __restrict__ b2v,
    float* __restrict__ C0, float* __restrict__ C1, float* __restrict__ C2,
    int M, int N, int K, float scale0, int do_round)
{
    __shared__ __nv_bfloat16 Ash[2][128 * AKP];
    __shared__ __nv_bfloat16 Bsh[2][32 * BNP];

    const float* A;  const float* Wm; const float* bias; float* C;
    if (blockIdx.z == 0)      { A = A0; Wm = W0; bias = b0v; C = C0; }
    else if (blockIdx.z == 1) { A = A1; Wm = W1; bias = b1v; C = C1; }
    else                      { A = A2; Wm = W2; bias = b2v; C = C2; }
    const float osc = (blockIdx.z == 0) ? scale0 : 1.f;

    const int t = threadIdx.x;
    const int lane = t & 31, wid = t >> 5;
    const int warp_m = wid & 3, warp_n = wid >> 2;
    const int m_w = warp_m * 32, n_w = warp_n * 64;
    const int bm = blockIdx.y * 128, bn = blockIdx.x * 128;
    const int gid = lane >> 2, tig = lane & 3;

    const int b_n0 = (t & 63) * 2;
    const int b_kq = (t >> 6) * 8;

    float acc[2][8][4];
    #pragma unroll
    for (int mt = 0; mt < 2; mt++)
        #pragma unroll
        for (int nt = 0; nt < 8; nt++)
            #pragma unroll
            for (int e = 0; e < 4; e++) acc[mt][nt][e] = 0.f;

    // ---- initial prefetch (k0 = 0)
    float4 a_pre[4];
    float2 b_pre[8];
    #pragma unroll
    for (int r = 0; r < 4; r++) {
        int e = t + r * 256;
        int row = e >> 3, col4 = (e & 7) << 2;
        a_pre[r] = *(const float4*)&A[(size_t)(bm + row) * K + col4];
    }
    #pragma unroll
    for (int kk = 0; kk < 8; kk++)
        b_pre[kk] = *(const float2*)&Wm[(size_t)(b_kq + kk) * N + bn + b_n0];

    for (int k0 = 0; k0 < K; k0 += 32) {
        // ---- convert + store staged registers to smem (hi/lo planes)
        #pragma unroll
        for (int r = 0; r < 4; r++) {
            int e = t + r * 256;
            int row = e >> 3, col4 = (e & 7) << 2;
            float4 v = a_pre[r];
            __nv_bfloat162 h0 = __floats2bfloat162_rn(v.x, v.y);
            __nv_bfloat162 h1 = __floats2bfloat162_rn(v.z, v.w);
            float2 f0 = __bfloat1622float2(h0);
            float2 f1 = __bfloat1622float2(h1);
            __nv_bfloat162 l0 = __floats2bfloat162_rn(v.x - f0.x, v.y - f0.y);
            __nv_bfloat162 l1 = __floats2bfloat162_rn(v.z - f1.x, v.w - f1.y);
            *(__nv_bfloat162*)&Ash[0][row * AKP + col4]     = h0;
            *(__nv_bfloat162*)&Ash[0][row * AKP + col4 + 2] = h1;
            *(__nv_bfloat162*)&Ash[1][row * AKP + col4]     = l0;
            *(__nv_bfloat162*)&Ash[1][row * AKP + col4 + 2] = l1;
        }
        #pragma unroll
        for (int kk = 0; kk < 8; kk++) {
            int k = b_kq + kk;
            float2 v = b_pre[kk];
            __nv_bfloat162 h = __floats2bfloat162_rn(v.x, v.y);
            float2 f = __bfloat1622float2(h);
            __nv_bfloat162 l = __floats2bfloat162_rn(v.x - f.x, v.y - f.y);
            *(__nv_bfloat162*)&Bsh[0][k * BNP + b_n0] = h;
            *(__nv_bfloat162*)&Bsh[1][k * BNP + b_n0] = l;
        }
        __syncthreads();

        // ---- prefetch next k-tile while computing this one
        if (k0 + 32 < K) {
            #pragma unroll
            for (int r = 0; r < 4; r++) {
                int e = t + r * 256;
                int row = e >> 3, col4 = (e & 7) << 2;
                a_pre[r] = *(const float4*)&A[(size_t)(bm + row) * K + k0 + 32 + col4];
            }
            #pragma unroll
            for (int kk = 0; kk < 8; kk++)
                b_pre[kk] = *(const float2*)&Wm[(size_t)(k0 + 32 + b_kq + kk) * N + bn + b_n0];
        }

        // ---- compute: 2 k-blocks of 16
        #pragma unroll
        for (int kb = 0; kb < 32; kb += 16) {
            uint32_t af[2][2][4];   // [mt][plane][reg]
            #pragma unroll
            for (int mt = 0; mt < 2; mt++) {
                const int arow = m_w + mt * 16 + (lane & 15);
                const int acol = kb + ((lane >> 4) << 3);
                #pragma unroll
                for (int p = 0; p < 2; p++) {
                    uint32_t addr = (uint32_t)__cvta_generic_to_shared(
                        &Ash[p][arow * AKP + acol]);
                    ldsm_x4(af[mt][p][0], af[mt][p][1], af[mt][p][2], af[mt][p][3], addr);
                }
            }
            #pragma unroll
            for (int nt = 0; nt < 8; nt++) {
                const int brow = kb + (lane & 15);
                const int bcol = n_w + nt * 8;
                uint32_t bh0, bh1, bl0, bl1;
                uint32_t addrh = (uint32_t)__cvta_generic_to_shared(
                    &Bsh[0][brow * BNP + bcol]);
                uint32_t addrl = (uint32_t)__cvta_generic_to_shared(
                    &Bsh[1][brow * BNP + bcol]);
                ldsm_x2_t(bh0, bh1, addrh);
                ldsm_x2_t(bl0, bl1, addrl);
                #pragma unroll
                for (int mt = 0; mt < 2; mt++) {
                    mma_bf16(acc[mt][nt], af[mt][0][0], af[mt][0][1],
                             af[mt][0][2], af[mt][0][3], bh0, bh1);
                    mma_bf16(acc[mt][nt], af[mt][1][0], af[mt][1][1],
                             af[mt][1][2], af[mt][1][3], bh0, bh1);
                    mma_bf16(acc[mt][nt], af[mt][0][0], af[mt][0][1],
                             af[mt][0][2], af[mt][0][3], bl0, bl1);
                }
            }
        }
        __syncthreads();
    }

    // ---- epilogue: + bias, optional scale + tf32 round, store
    #pragma unroll
    for (int mt = 0; mt < 2; mt++) {
        const int row0 = bm + m_w + mt * 16 + gid;
        #pragma unroll
        for (int nt = 0; nt < 8; nt++) {
            const int col = bn + n_w + nt * 8 + tig * 2;
            float2 bb = *(const float2*)&bias[col];
            float2 o0 = make_float2((acc[mt][nt][0] + bb.x) * osc,
                                    (acc[mt][nt][1] + bb.y) * osc);
            float2 o1 = make_float2((acc[mt][nt][2] + bb.x) * osc,
                                    (acc[mt][nt][3] + bb.y) * osc);
            if (do_round) {
                o0.x = tf32f(o0.x); o0.y = tf32f(o0.y);
                o1.x = tf32f(o1.x); o1.y = tf32f(o1.y);
            }
            *(float2*)&C[(size_t)row0 * N + col]       = o0;
            *(float2*)&C[(size_t)(row0 + 8) * N + col] = o1;
        }
    }
}

// ---------------------------------------------------------------------------
// Prep: detect all-zero biases; precompute collapsed coefficients
// ---------------------------------------------------------------------------
__global__ void prep_kernel(const float* __restrict__ tm_w, const float* __restrict__ tm_b,
                            const float* __restrict__ dm_w, const float* __restrict__ dm_b,
                            const float* __restrict__ td_w)
{
    const int l = threadIdx.x;   // 32 threads
    float ct = 0.f, cd = 0.f;
    bool z = true;
    #pragma unroll
    for (int m = l; m < 64; m += 32) {
        z = z && (tm_b[m] == 0.f) && (dm_b[m] == 0.f);
        ct += 0.5f * td_w[m] * fmaxf(tm_w[m], 0.f);
        cd += 0.5f * td_w[m] * fmaxf(dm_w[m], 0.f);
    }
    unsigned bz = __ballot_sync(0xffffffffu, z);
    #pragma unroll
    for (int o = 16; o; o >>= 1) {
        ct += __shfl_xor_sync(0xffffffffu, ct, o);
        cd += __shfl_xor_sync(0xffffffffu, cd, o);
    }
    if (l == 0) { g_Ct = ct; g_Cd = cd; g_bzero = (bz == 0xffffffffu); }
}

// ---------------------------------------------------------------------------
// Fused bias + mask. Fast path (biases all zero): 2 FMAs per element.
// ---------------------------------------------------------------------------
__global__ __launch_bounds__(256) void bias_mask_kernel(
    const float* __restrict__ tmat, const float* __restrict__ dmat,
    const int*   __restrict__ mask,
    const float* __restrict__ tm_w, const float* __restrict__ tm_b,
    const float* __restrict__ dm_w, const float* __restrict__ dm_b,
    const float* __restrict__ td_w, const float* __restrict__ td_b)
{
    const int t = threadIdx.x;
    const float tdb = td_b[0];
    const float E = 2.718281828459045f;

    const size_t base = ((size_t)blockIdx.x * 256 + t) * 4;
    float4 u  = *(const float4*)(tmat + base);
    float4 w  = *(const float4*)(dmat + base);
    int4   mk = *(const int4*)(mask + base);

    float tv[4] = { 1.f / __logf(E + u.x), 1.f / __logf(E + u.y),
                    1.f / __logf(E + u.z), 1.f / __logf(E + u.w) };
    float dv[4] = { 1.f / __logf(E + w.x), 1.f / __logf(E + w.y),
                    1.f / __logf(E + w.z), 1.f / __logf(E + w.w) };
    float acc[4];

    if (g_bzero) {
        const float Ct = g_Ct, Cd = g_Cd;
        #pragma unroll
        for (int i = 0; i < 4; i++)
            acc[i] = fmaf(tv[i], Ct, fmaf(dv[i], Cd, tdb));
    } else {
        __shared__ float sp[5][64];
        if (t < 64) {
            sp[0][t] = tm_w[t];
            sp[1][t] = tm_b[t];
            sp[2][t] = dm_w[t];
            sp[3][t] = dm_b[t];
            sp[4][t] = td_w[t] * 0.5f;
        }
        __syncthreads();
        #pragma unroll
        for (int i = 0; i < 4; i++) acc[i] = tdb;
        #pragma unroll 8
        for (int m = 0; m < 64; m++) {
            const float tw = sp[0][m], tb = sp[1][m];
            const float dw = sp[2][m], db = sp[3][m];
            const float ww = sp[4][m];
            #pragma unroll
            for (int i = 0; i < 4; i++) {
                float rt = fmaxf(tv[i] * tw + tb, 0.f);
                float rd = fmaxf(dv[i] * dw + db, 0.f);
                acc[i] += ww * (rt + rd);
            }
        }
    }

    float4 o;
    o.x = (mk.x == 1) ? -1e9f : acc[0];
    o.y = (mk.y == 1) ? -1e9f : acc[1];
    o.z = (mk.z == 1) ? -1e9f : acc[2];
    o.w = (mk.w == 1) ? -1e9f : acc[3];
    *(float4*)(g_bias + base) = o;
}

// ---------------------------------------------------------------------------
// Flash attention, TF32 tensor cores, cp.async double-buffered K/V.
// g_q is pre-scaled (1/8) and tf32-rounded; g_k/g_v tf32-rounded — so tiles
// stream straight global -> smem with no conversion pass.
// ---------------------------------------------------------------------------
#define QS 68
#define VS 72
#define SM_P  (64*QS)
#define SM_K  (2*64*QS)
#define SM_V  (4*64*QS)
#define SMEM_ATTN ((4*64*QS + 2*64*VS)*4)

__global__ __launch_bounds__(128) void attn_tf32()
{
    extern __shared__ float smn[];
    float* Qs = smn;

    const int qt = blockIdx.x, h = blockIdx.y, b = blockIdx.z;
    const int t = threadIdx.x;
    const int w = t >> 5, lane = t & 31;
    const int gid = lane >> 2, tig = lane & 3;
    const int q0 = qt * 64, hoff = h * DK_;
    const int r0 = w * 16 + gid;

    const int ld_row = t >> 4;           // 0..7  (row group for copies)
    const int ld_c4  = (t & 15) << 2;    // 0..60 (float offset)

    // ---- prologue: async-copy Q tile + K/V tile 0 (one group)
    #pragma unroll
    for (int r = 0; r < 8; r++) {
        int row = ld_row + r * 8;
        cpa16((uint32_t)__cvta_generic_to_shared(&Qs[row * QS + ld_c4]),
              &g_q[(size_t)(b * S_ + q0 + row) * D_ + hoff + ld_c4]);
    }
    {
        float* Kb = smn + SM_K;
        float* Vb = smn + SM_V;
        #pragma unroll
        for (int r = 0; r < 8; r++) {
            int row = ld_row + r * 8;
            size_t g = (size_t)(b * S_ + row) * D_ + hoff + ld_c4;
            cpa16((uint32_t)__cvta_generic_to_shared(&Kb[row * QS + ld_c4]), &g_k[g]);
            cpa16((uint32_t)__cvta_generic_to_shared(&Vb[row * VS + ld_c4]), &g_v[g]);
        }
    }
    cp_commit();

    float m0 = -1e30f, m1 = -1e30f, l0 = 0.f, l1 = 0.f;
    float oacc[8][4];
    #pragma unroll
    for (int nt = 0; nt < 8; nt++)
        #pragma unroll
        for (int e = 0; e < 4; e++) oacc[nt][e] = 0.f;

    const float* biasA = g_bias + ((size_t)b * S_ + q0 + r0) * S_;
    const float* biasB = biasA + (size_t)8 * S_;

    for (int kt = 0; kt < 16; kt++) {
        const int buf = kt & 1;
        // ---- issue next tile's copies, then wait for current tile
        if (kt < 15) {
            const int k1 = (kt + 1) * 64;
            float* Kb = smn + SM_K + (buf ^ 1) * 64 * QS;
            float* Vb = smn + SM_V + (buf ^ 1) * 64 * VS;
            #pragma unroll
            for (int r = 0; r < 8; r++) {
                int row = ld_row + r * 8;
                size_t g = (size_t)(b * S_ + k1 + row) * D_ + hoff + ld_c4;
                cpa16((uint32_t)__cvta_generic_to_shared(&Kb[row * QS + ld_c4]), &g_k[g]);
                cpa16((uint32_t)__cvta_generic_to_shared(&Vb[row * VS + ld_c4]), &g_v[g]);
            }
            cp_commit();
            cp_wait<1>();
        } else {
            cp_wait<0>();
        }
        __syncthreads();

        const float* Ks = smn + SM_K + buf * 64 * QS;
        const float* Vs = smn + SM_V + buf * 64 * VS;
        float* Ps = smn + SM_P;
        const int k0 = kt * 64;

        // ---- scores S = Q @ K^T (Q pre-scaled by 1/8)
        float sacc[8][4];
        #pragma unroll
        for (int nt = 0; nt < 8; nt++)
            #pragma unroll
            for (int e = 0; e < 4; e++) sacc[nt][e] = 0.f;

        const float* qa = &Qs[r0 * QS + tig];
        const float* kb = &Ks[gid * QS + tig];
        #pragma unroll
        for (int d8 = 0; d8 < 8; d8++) {
            const int d0 = d8 * 8;
            uint32_t a0 = __float_as_uint(qa[d0]);
            uint32_t a1 = __float_as_uint(qa[8 * QS + d0]);
            uint32_t a2 = __float_as_uint(qa[d0 + 4]);
            uint32_t a3 = __float_as_uint(qa[8 * QS + d0 + 4]);
            #pragma unroll
            for (int nt = 0; nt < 8; nt++) {
                uint32_t b0 = __float_as_uint(kb[nt * 8 * QS + d0]);
                uint32_t b1 = __float_as_uint(kb[nt * 8 * QS + d0 + 4]);
                mma_tf32(sacc[nt], a0, a1, a2, a3, b0, b1);
            }
        }

        // ---- + bias (mask folded as -1e9) + row max
        float mx0 = -1e30f, mx1 = -1e30f;
        #pragma unroll
        for (int nt = 0; nt < 8; nt++) {
            float2 ba = *(const float2*)&biasA[k0 + nt * 8 + tig * 2];
            float2 bb = *(const float2*)&biasB[k0 + nt * 8 + tig * 2];
            sacc[nt][0] += ba.x;
            sacc[nt][1] += ba.y;
            sacc[nt][2] += bb.x;
            sacc[nt][3] += bb.y;
            mx0 = fmaxf(mx0, fmaxf(sacc[nt][0], sacc[nt][1]));
            mx1 = fmaxf(mx1, fmaxf(sacc[nt][2], sacc[nt][3]));
        }
        mx0 = fmaxf(mx0, __shfl_xor_sync(0xffffffffu, mx0, 1));
        mx0 = fmaxf(mx0, __shfl_xor_sync(0xffffffffu, mx0, 2));
        mx1 = fmaxf(mx1, __shfl_xor_sync(0xffffffffu, mx1, 1));
        mx1 = fmaxf(mx1, __shfl_xor_sync(0xffffffffu, mx1, 2));

        const float mn0 = fmaxf(m0, mx0), mn1 = fmaxf(m1, mx1);
        const float c0 = __expf(m0 - mn0), c1 = __expf(m1 - mn1);
        m0 = mn0; m1 = mn1;

        float rs0 = 0.f, rs1 = 0.f;
        #pragma unroll
        for (int nt = 0; nt < 8; nt++) {
            sacc[nt][0] = __expf(sacc[nt][0] - mn0);
            sacc[nt][1] = __expf(sacc[nt][1] - mn0);
            sacc[nt][2] = __expf(sacc[nt][2] - mn1);
            sacc[nt][3] = __expf(sacc[nt][3] - mn1);
            rs0 += sacc[nt][0] + sacc[nt][1];
            rs1 += sacc[nt][2] + sacc[nt][3];
        }
        rs0 += __shfl_xor_sync(0xffffffffu, rs0, 1);
        rs0 += __shfl_xor_sync(0xffffffffu, rs0, 2);
        rs1 += __shfl_xor_sync(0xffffffffu, rs1, 1);
        rs1 += __shfl_xor_sync(0xffffffffu, rs1, 2);

        l0 = l0 * c0 + rs0;
        l1 = l1 * c1 + rs1;
        #pragma unroll
        for (int nt = 0; nt < 8; nt++) {
            oacc[nt][0] *= c0; oacc[nt][1] *= c0;
            oacc[nt][2] *= c1; oacc[nt][3] *= c1;
        }

        // ---- stage P to warp-private smem (tf32-rounded)
        float* pr0 = &Ps[r0 * QS];
        float* pr1 = &Ps[(r0 + 8) * QS];
        #pragma unroll
        for (int nt = 0; nt < 8; nt++) {
            pr0[nt * 8 + tig * 2]     = tf32f(sacc[nt][0]);
            pr0[nt * 8 + tig * 2 + 1] = tf32f(sacc[nt][1]);
            pr1[nt * 8 + tig * 2]     = tf32f(sacc[nt][2]);
            pr1[nt * 8 + tig * 2 + 1] = tf32f(sacc[nt][3]);
        }
        __syncwarp();

        // ---- O += P @ V
        const float* pa = &Ps[r0 * QS + tig];
        const float* vb = &Vs[tig * VS + gid];
        #pragma unroll
        for (int j8 = 0; j8 < 8; j8++) {
            const int j0 = j8 * 8;
            uint32_t a0 = __float_as_uint(pa[j0]);
            uint32_t a1 = __float_as_uint(pa[8 * QS + j0]);
            uint32_t a2 = __float_as_uint(pa[j0 + 4]);
            uint32_t a3 = __float_as_uint(pa[8 * QS + j0 + 4]);
            #pragma unroll
            for (int nt = 0; nt < 8; nt++) {
                uint32_t b0 = __float_as_uint(vb[j0 * VS + nt * 8]);
                uint32_t b1 = __float_as_uint(vb[(j0 + 4) * VS + nt * 8]);
                mma_tf32(oacc[nt], a0, a1, a2, a3, b0, b1);
            }
        }
        __syncthreads();   // all reads of buf done before it is refilled
    }

    // ---- epilogue: normalize, write [B,S,D]
    const float inv0 = 1.f / l0, inv1 = 1.f / l1;
    float* out0 = &g_attn[(size_t)(b * S_ + q0 + r0) * D_ + hoff];
    float* out1 = &g_attn[(size_t)(b * S_ + q0 + r0 + 8) * D_ + hoff];
    #pragma unroll
    for (int nt = 0; nt < 8; nt++) {
        float2 o0 = make_float2(oacc[nt][0] * inv0, oacc[nt][1] * inv0);
        float2 o1 = make_float2(oacc[nt][2] * inv1, oacc[nt][3] * inv1);
        *(float2*)&out0[nt * 8 + tig * 2] = o0;
        *(float2*)&out1[nt * 8 + tig * 2] = o1;
    }
}

// ---------------------------------------------------------------------------
extern "C" void kernel_launch(void* const* d_in, const int* in_sizes, int n_in,
                              void* d_out, int out_size)
{
    const float* Q     = (const float*)d_in[0];
    const float* K     = (const float*)d_in[1];
    const float* V     = (const float*)d_in[2];
    const float* tmat  = (const float*)d_in[3];
    const float* dmat  = (const float*)d_in[4];
    const int*   mask  = (const int*)  d_in[5];
    const float* Wq    = (const float*)d_in[6];
    const float* bq    = (const float*)d_in[7];
    const float* Wk    = (const float*)d_in[8];
    const float* bk    = (const float*)d_in[9];
    const float* Wv    = (const float*)d_in[10];
    const float* bv    = (const float*)d_in[11];
    const float* Wo    = (const float*)d_in[12];
    const float* bo    = (const float*)d_in[13];
    const float* tm_w  = (const float*)d_in[14];
    const float* tm_b  = (const float*)d_in[15];
    const float* dm_w  = (const float*)d_in[16];
    const float* dm_b  = (const float*)d_in[17];
    const float* td_w  = (const float*)d_in[18];
    const float* td_b  = (const float*)d_in[19];
    float* out = (float*)d_out;

    float *qb, *kb, *vb, *ab;
    cudaGetSymbolAddress((void**)&qb, g_q);
    cudaGetSymbolAddress((void**)&kb, g_k);
    cudaGetSymbolAddress((void**)&vb, g_v);
    cudaGetSymbolAddress((void**)&ab, g_attn);

    prep_kernel<<<1, 32>>>(tm_w, tm_b, dm_w, dm_b, td_w);

    // fused Q/K/V projections (z = 3): outputs tf32-rounded, Q pre-scaled
    gemm_qkv<<<dim3(D_ / 128, MTOT / 128, 3), 256>>>(
        Q, K, V, Wq, Wk, Wv, bq, bk, bv, qb, kb, vb, MTOT, D_, D_, 0.125f, 1);

    bias_mask_kernel<<<(B_ * S_ * S_) / 1024, 256>>>(
        tmat, dmat, mask, tm_w, tm_b, dm_w, dm_b, td_w, td_b);

    cudaFuncSetAttribute(attn_tf32,
                         cudaFuncAttributeMaxDynamicSharedMemorySize, SMEM_ATTN);
    attn_tf32<<<dim3(S_ / 64, H_, B_), 128, SMEM_ATTN>>>();

    // output projection (z = 1; reuse fused kernel, slot 0), plain fp32 out
    gemm_qkv<<<dim3(D_ / 128, MTOT / 128, 1), 256>>>(
        ab, ab, ab, Wo, Wo, Wo, bo, bo, bo, out, out, out, MTOT, D_, D_, 1.f, 0);
}